// round 5
// baseline (speedup 1.0000x reference)
#include <cuda_runtime.h>
#include <math.h>

// Problem constants
#define BSZ 4
#define SEQ 2048
#define EMB 1024
#define NH  16
#define HD  64
#define MTOT (BSZ*SEQ)   // 8192

// Scratch (device globals — no allocation allowed)
__device__ float g_Q[BSZ*NH*SEQ*HD];     // 32 MB
__device__ float g_K[BSZ*NH*SEQ*HD];     // 32 MB
__device__ float g_V[BSZ*NH*SEQ*HD];     // 32 MB
__device__ float g_AO[BSZ*SEQ*EMB];      // 32 MB  attention output, [b][s][h*64+d]
__device__ float g_cos[SEQ*32];
__device__ float g_sin[SEQ*32];

// ---------------- packed f32x2 helpers (sm_103a FFMA2 pipe) ----------------
__device__ __forceinline__ unsigned long long ffma2(unsigned long long a,
                                                    unsigned long long b,
                                                    unsigned long long c) {
    unsigned long long d;
    asm("fma.rn.f32x2 %0, %1, %2, %3;" : "=l"(d) : "l"(a), "l"(b), "l"(c));
    return d;
}
__device__ __forceinline__ unsigned long long fmul2(unsigned long long a,
                                                    unsigned long long b) {
    unsigned long long d;
    asm("mul.rn.f32x2 %0, %1, %2;" : "=l"(d) : "l"(a), "l"(b));
    return d;
}
__device__ __forceinline__ unsigned long long fdup2(float x) {
    unsigned long long r;
    asm("mov.b64 %0, {%1, %2};" : "=l"(r) : "f"(x), "f"(x));
    return r;
}
__device__ __forceinline__ float2 funpack2(unsigned long long v) {
    float2 f;
    asm("mov.b64 {%0, %1}, %2;" : "=f"(f.x), "=f"(f.y) : "l"(v));
    return f;
}

// ---------------- GEMM: C[M,N] = A[M,1024] @ W[N,1024]^T + bias ----------------
// MODE 0: A = hidden, scatter into g_Q/g_K/g_V  (N=3072)
// MODE 1: A = g_AO, write to out row-major       (N=1024)
template<int MODE, int N>
__global__ __launch_bounds__(256)
void gemm_kernel(const float* __restrict__ A, const float* __restrict__ W,
                 const float* __restrict__ bias, float* __restrict__ out)
{
    constexpr int K = 1024;
    __shared__ float As[16][132];   // [k][m], padded
    __shared__ float Bs[16][132];   // [k][n], padded

    const int tid = threadIdx.x;
    const int m0 = blockIdx.y * 128;
    const int n0 = blockIdx.x * 128;
    const int ty = tid >> 4;        // 0..15, rows ty*8..+7
    const int tx = tid & 15;        // 0..15, cols tx*8..+7

    const float* __restrict__ Ap = (MODE == 0) ? A : g_AO;

    unsigned long long acc[4][8];
    #pragma unroll
    for (int i = 0; i < 4; i++)
        #pragma unroll
        for (int j = 0; j < 8; j++) acc[i][j] = 0ull;

    const int lrow = tid >> 2;        // 0..63
    const int lk   = (tid & 3) * 4;   // 0,4,8,12

    for (int kt = 0; kt < K; kt += 16) {
        #pragma unroll
        for (int it = 0; it < 2; it++) {
            const int row = lrow + it * 64;
            float4 av = *(const float4*)&Ap[(m0 + row) * K + kt + lk];
            As[lk+0][row] = av.x; As[lk+1][row] = av.y;
            As[lk+2][row] = av.z; As[lk+3][row] = av.w;
            float4 bv = *(const float4*)&W[(n0 + row) * K + kt + lk];
            Bs[lk+0][row] = bv.x; Bs[lk+1][row] = bv.y;
            Bs[lk+2][row] = bv.z; Bs[lk+3][row] = bv.w;
        }
        __syncthreads();
        #pragma unroll
        for (int k = 0; k < 16; k++) {
            ulonglong2 a01 = *(const ulonglong2*)&As[k][ty*8];
            ulonglong2 a23 = *(const ulonglong2*)&As[k][ty*8 + 4];
            unsigned long long ap[4] = {a01.x, a01.y, a23.x, a23.y};
            float4 b0 = *(const float4*)&Bs[k][tx*8];
            float4 b1 = *(const float4*)&Bs[k][tx*8 + 4];
            unsigned long long bd[8] = {fdup2(b0.x), fdup2(b0.y), fdup2(b0.z), fdup2(b0.w),
                                        fdup2(b1.x), fdup2(b1.y), fdup2(b1.z), fdup2(b1.w)};
            #pragma unroll
            for (int i = 0; i < 4; i++)
                #pragma unroll
                for (int j = 0; j < 8; j++)
                    acc[i][j] = ffma2(ap[i], bd[j], acc[i][j]);
        }
        __syncthreads();
    }

    #pragma unroll
    for (int i = 0; i < 4; i++) {
        const int m = m0 + ty*8 + i*2;   // pair covers rows m, m+1
        #pragma unroll
        for (int j = 0; j < 8; j++) {
            const int n = n0 + tx*8 + j;
            float2 v = funpack2(acc[i][j]);
            const float bb = bias[n];
            const float v0 = v.x + bb, v1 = v.y + bb;
            if (MODE == 1) {
                out[m * N + n]       = v0;
                out[(m + 1) * N + n] = v1;
            } else {
                const int which = n >> 10, r = n & 1023;
                const int h = r >> 6, d = r & 63;
                float* dst = (which == 0) ? g_Q : (which == 1) ? g_K : g_V;
                const int b = m >> 11, s = m & 2047;  // 128-row tiles never cross batch
                const int off = ((b * NH + h) * SEQ + s) * HD + d;
                dst[off]      = v0;
                dst[off + HD] = v1;   // row m+1 -> s+1
            }
        }
    }
}

// ---------------- RoPE table: fp64-exact, rounded to fp32 ----------------
__global__ void rope_table_kernel() {
    const int idx = blockIdx.x * blockDim.x + threadIdx.x;  // 65536
    const int d = idx & 31, s = idx >> 5;
    const double inv = exp(-((double)d / 32.0) * log(10000.0));
    const float ang = (float)s * (float)inv;   // fp32 mult matches reference
    g_cos[idx] = (float)cos((double)ang);
    g_sin[idx] = (float)sin((double)ang);
}

// ---------------- RoPE apply (in-place on g_Q, g_K) ----------------
__global__ __launch_bounds__(256) void rope_kernel() {
    const int idx = blockIdx.x * 256 + threadIdx.x;  // BSZ*NH*SEQ*32 = 4194304
    const int d  = idx & 31;
    const int s  = (idx >> 5) & 2047;
    const int bh = idx >> 16;
    const int base = (bh * SEQ + s) * HD + d;
    const float c  = g_cos[(s << 5) + d];
    const float sn = g_sin[(s << 5) + d];
    const float q1 = g_Q[base], q2 = g_Q[base + 32];
    g_Q[base]      = q1 * c - q2 * sn;
    g_Q[base + 32] = q2 * c + q1 * sn;
    const float k1 = g_K[base], k2 = g_K[base + 32];
    g_K[base]      = k1 * c - k2 * sn;
    g_K[base + 32] = k2 * c + k1 * sn;
}

// ---------------- Flash attention (fp32, FFMA2 matmuls) ----------------
// grid (32 q-tiles, 64 bh), 256 threads. 64x64 tiles, hd=64.
__global__ __launch_bounds__(256)
void attn_kernel()
{
    __shared__ float Qs[64][64];   // [m][d], pre-scaled
    __shared__ float KP[64][64];   // K transposed [d][c]; reused as P [m][c]
    __shared__ float Vs[64][64];   // [c][d]

    const int tid = threadIdx.x;
    const int qt  = blockIdx.x;
    const int bh  = blockIdx.y;
    const int qbase = (bh * SEQ + qt * 64) * HD;
    const int kbase = bh * SEQ * HD;

    const int lr = tid >> 4;          // 0..15
    const int lc = (tid & 15) * 4;

    #pragma unroll
    for (int it = 0; it < 4; it++) {
        const int row = lr + it * 16;
        float4 v = *(const float4*)&g_Q[qbase + row * 64 + lc];
        v.x *= 0.125f; v.y *= 0.125f; v.z *= 0.125f; v.w *= 0.125f;
        *(float4*)&Qs[row][lc] = v;
    }

    const int ty = tid >> 3;          // 0..31, rows ty*2..+1
    const int tx = tid & 7;           // 0..7, cols tx*8..+7
    const int r0 = ty * 2;
    const int c0 = tx * 8;

    float mrow0 = -INFINITY, mrow1 = -INFINITY;
    float lrow0 = 0.f, lrow1 = 0.f;
    unsigned long long oacc[2][4];
    #pragma unroll
    for (int i = 0; i < 2; i++)
        #pragma unroll
        for (int j = 0; j < 4; j++) oacc[i][j] = 0ull;

    for (int t = 0; t < 32; t++) {
        __syncthreads();   // previous-iter KP/Vs reads done (also covers Qs fill at t=0)
        #pragma unroll
        for (int it = 0; it < 4; it++) {
            const int row = lr + it * 16;
            float4 kv = *(const float4*)&g_K[kbase + (t * 64 + row) * 64 + lc];
            KP[lc+0][row] = kv.x; KP[lc+1][row] = kv.y;
            KP[lc+2][row] = kv.z; KP[lc+3][row] = kv.w;
            *(float4*)&Vs[row][lc] = *(const float4*)&g_V[kbase + (t * 64 + row) * 64 + lc];
        }
        __syncthreads();

        // S = Qs @ K^T  (rows r0..r0+1, key cols c0..c0+7, packed along keys)
        unsigned long long sacc[2][4];
        #pragma unroll
        for (int i = 0; i < 2; i++)
            #pragma unroll
            for (int j = 0; j < 4; j++) sacc[i][j] = 0ull;

        #pragma unroll 16
        for (int d = 0; d < 64; d++) {
            ulonglong2 k01 = *(const ulonglong2*)&KP[d][c0];
            ulonglong2 k23 = *(const ulonglong2*)&KP[d][c0 + 4];
            unsigned long long q0 = fdup2(Qs[r0][d]);
            unsigned long long q1 = fdup2(Qs[r0 + 1][d]);
            sacc[0][0] = ffma2(q0, k01.x, sacc[0][0]);
            sacc[0][1] = ffma2(q0, k01.y, sacc[0][1]);
            sacc[0][2] = ffma2(q0, k23.x, sacc[0][2]);
            sacc[0][3] = ffma2(q0, k23.y, sacc[0][3]);
            sacc[1][0] = ffma2(q1, k01.x, sacc[1][0]);
            sacc[1][1] = ffma2(q1, k01.y, sacc[1][1]);
            sacc[1][2] = ffma2(q1, k23.x, sacc[1][2]);
            sacc[1][3] = ffma2(q1, k23.y, sacc[1][3]);
        }

        // online softmax (row stats across the 8 threads of a ty-group)
        float p[2][8];
        #pragma unroll
        for (int i = 0; i < 2; i++) {
            float sv[8];
            float2 u;
            u = funpack2(sacc[i][0]); sv[0] = u.x; sv[1] = u.y;
            u = funpack2(sacc[i][1]); sv[2] = u.x; sv[3] = u.y;
            u = funpack2(sacc[i][2]); sv[4] = u.x; sv[5] = u.y;
            u = funpack2(sacc[i][3]); sv[6] = u.x; sv[7] = u.y;
            float rmax = sv[0];
            #pragma unroll
            for (int j = 1; j < 8; j++) rmax = fmaxf(rmax, sv[j]);
            #pragma unroll
            for (int o = 4; o > 0; o >>= 1)
                rmax = fmaxf(rmax, __shfl_xor_sync(0xffffffffu, rmax, o, 8));
            const float mold = (i == 0) ? mrow0 : mrow1;
            const float mnew = fmaxf(mold, rmax);
            const float corr = __expf(mold - mnew);
            float rsum = 0.f;
            #pragma unroll
            for (int j = 0; j < 8; j++) { p[i][j] = __expf(sv[j] - mnew); rsum += p[i][j]; }
            #pragma unroll
            for (int o = 4; o > 0; o >>= 1)
                rsum += __shfl_xor_sync(0xffffffffu, rsum, o, 8);
            if (i == 0) { mrow0 = mnew; lrow0 = lrow0 * corr + rsum; }
            else        { mrow1 = mnew; lrow1 = lrow1 * corr + rsum; }
            const unsigned long long cd = fdup2(corr);
            oacc[i][0] = fmul2(oacc[i][0], cd);
            oacc[i][1] = fmul2(oacc[i][1], cd);
            oacc[i][2] = fmul2(oacc[i][2], cd);
            oacc[i][3] = fmul2(oacc[i][3], cd);
        }

        __syncthreads();   // all KP reads done -> reuse as P buffer
        *(float4*)&KP[r0][c0]       = make_float4(p[0][0], p[0][1], p[0][2], p[0][3]);
        *(float4*)&KP[r0][c0 + 4]   = make_float4(p[0][4], p[0][5], p[0][6], p[0][7]);
        *(float4*)&KP[r0+1][c0]     = make_float4(p[1][0], p[1][1], p[1][2], p[1][3]);
        *(float4*)&KP[r0+1][c0 + 4] = make_float4(p[1][4], p[1][5], p[1][6], p[1][7]);
        __syncthreads();

        // O += P @ V  (rows r0..r0+1, d cols c0..c0+7, packed along d)
        #pragma unroll 16
        for (int c = 0; c < 64; c++) {
            ulonglong2 v01 = *(const ulonglong2*)&Vs[c][c0];
            ulonglong2 v23 = *(const ulonglong2*)&Vs[c][c0 + 4];
            unsigned long long p0 = fdup2(KP[r0][c]);
            unsigned long long p1 = fdup2(KP[r0 + 1][c]);
            oacc[0][0] = ffma2(p0, v01.x, oacc[0][0]);
            oacc[0][1] = ffma2(p0, v01.y, oacc[0][1]);
            oacc[0][2] = ffma2(p0, v23.x, oacc[0][2]);
            oacc[0][3] = ffma2(p0, v23.y, oacc[0][3]);
            oacc[1][0] = ffma2(p1, v01.x, oacc[1][0]);
            oacc[1][1] = ffma2(p1, v01.y, oacc[1][1]);
            oacc[1][2] = ffma2(p1, v23.x, oacc[1][2]);
            oacc[1][3] = ffma2(p1, v23.y, oacc[1][3]);
        }
    }

    // finalize: g_AO[b][s][h*64+d]
    const int b = bh >> 4, h = bh & 15;
    const int obase = (b * SEQ + qt * 64 + r0) * EMB + h * 64 + c0;
    const float inv0 = 1.0f / lrow0;
    const float inv1 = 1.0f / lrow1;
    float2 u;
    float o[8];
    u = funpack2(oacc[0][0]); o[0] = u.x * inv0; o[1] = u.y * inv0;
    u = funpack2(oacc[0][1]); o[2] = u.x * inv0; o[3] = u.y * inv0;
    u = funpack2(oacc[0][2]); o[4] = u.x * inv0; o[5] = u.y * inv0;
    u = funpack2(oacc[0][3]); o[6] = u.x * inv0; o[7] = u.y * inv0;
    *(float4*)&g_AO[obase]     = make_float4(o[0], o[1], o[2], o[3]);
    *(float4*)&g_AO[obase + 4] = make_float4(o[4], o[5], o[6], o[7]);
    u = funpack2(oacc[1][0]); o[0] = u.x * inv1; o[1] = u.y * inv1;
    u = funpack2(oacc[1][1]); o[2] = u.x * inv1; o[3] = u.y * inv1;
    u = funpack2(oacc[1][2]); o[4] = u.x * inv1; o[5] = u.y * inv1;
    u = funpack2(oacc[1][3]); o[6] = u.x * inv1; o[7] = u.y * inv1;
    *(float4*)&g_AO[obase + EMB]     = make_float4(o[0], o[1], o[2], o[3]);
    *(float4*)&g_AO[obase + EMB + 4] = make_float4(o[4], o[5], o[6], o[7]);
}

// ---------------- launch ----------------
extern "C" void kernel_launch(void* const* d_in, const int* in_sizes, int n_in,
                              void* d_out, int out_size)
{
    const float* hidden = (const float*)d_in[0];
    const float* qkv_w  = (const float*)d_in[1];
    const float* qkv_b  = (const float*)d_in[2];
    const float* proj_w = (const float*)d_in[3];
    const float* proj_b = (const float*)d_in[4];
    float* out = (float*)d_out;

    // 1) QKV projection -> g_Q/g_K/g_V  (M=8192, N=3072, K=1024)
    gemm_kernel<0, 3072><<<dim3(24, 64), 256>>>(hidden, qkv_w, qkv_b, nullptr);

    // 2) RoPE table + apply
    rope_table_kernel<<<256, 256>>>();
    rope_kernel<<<(BSZ*NH*SEQ*32)/256, 256>>>();

    // 3) Attention -> g_AO
    attn_kernel<<<dim3(32, 64), 256>>>();

    // 4) Output projection -> d_out  (M=8192, N=1024, K=1024)
    gemm_kernel<1, 1024><<<dim3(8, 64), 256>>>(nullptr, proj_w, proj_b, out);
}

// round 7
// speedup vs baseline: 1.6463x; 1.6463x over previous
#include <cuda_runtime.h>
#include <math.h>

// Problem constants
#define BSZ 4
#define SEQ 2048
#define EMB 1024
#define NH  16
#define HD  64
#define MTOT (BSZ*SEQ)   // 8192

// Scratch (device globals — no allocation allowed)
__device__ float g_Q[BSZ*NH*SEQ*HD];     // 32 MB
__device__ float g_K[BSZ*NH*SEQ*HD];     // 32 MB
__device__ float g_V[BSZ*NH*SEQ*HD];     // 32 MB
__device__ float g_AO[BSZ*SEQ*EMB];      // 32 MB  attention output, [b][s][h*64+d]
__device__ float g_cos[SEQ*32];
__device__ float g_sin[SEQ*32];

// ---------------- packed f32x2 helpers (sm_103a FFMA2 pipe) ----------------
__device__ __forceinline__ unsigned long long ffma2(unsigned long long a,
                                                    unsigned long long b,
                                                    unsigned long long c) {
    unsigned long long d;
    asm("fma.rn.f32x2 %0, %1, %2, %3;" : "=l"(d) : "l"(a), "l"(b), "l"(c));
    return d;
}
__device__ __forceinline__ unsigned long long fmul2(unsigned long long a,
                                                    unsigned long long b) {
    unsigned long long d;
    asm("mul.rn.f32x2 %0, %1, %2;" : "=l"(d) : "l"(a), "l"(b));
    return d;
}
__device__ __forceinline__ unsigned long long fdup2(float x) {
    unsigned long long r;
    asm("mov.b64 %0, {%1, %2};" : "=l"(r) : "f"(x), "f"(x));
    return r;
}
__device__ __forceinline__ float2 funpack2(unsigned long long v) {
    float2 f;
    asm("mov.b64 {%0, %1}, %2;" : "=f"(f.x), "=f"(f.y) : "l"(v));
    return f;
}

// ---------------- GEMM: C[M,N] = A[M,1024] @ W[N,1024]^T + bias ----------------
// MODE 0: A = hidden, scatter into g_Q/g_K/g_V  (N=3072)
// MODE 1: A = g_AO, write to out row-major       (N=1024)
template<int MODE, int N>
__global__ __launch_bounds__(256)
void gemm_kernel(const float* __restrict__ A, const float* __restrict__ W,
                 const float* __restrict__ bias, float* __restrict__ out)
{
    constexpr int K = 1024;
    __shared__ float As[16][132];   // [k][m], padded
    __shared__ float Bs[16][132];   // [k][n], padded

    const int tid = threadIdx.x;
    const int m0 = blockIdx.y * 128;
    const int n0 = blockIdx.x * 128;
    const int ty = tid >> 4;        // 0..15, rows ty*8..+7
    const int tx = tid & 15;        // 0..15, cols tx*8..+7

    const float* __restrict__ Ap = (MODE == 0) ? A : g_AO;

    unsigned long long acc[4][8];
    #pragma unroll
    for (int i = 0; i < 4; i++)
        #pragma unroll
        for (int j = 0; j < 8; j++) acc[i][j] = 0ull;

    const int lrow = tid >> 2;        // 0..63
    const int lk   = (tid & 3) * 4;   // 0,4,8,12

    for (int kt = 0; kt < K; kt += 16) {
        #pragma unroll
        for (int it = 0; it < 2; it++) {
            const int row = lrow + it * 64;
            float4 av = *(const float4*)&Ap[(m0 + row) * K + kt + lk];
            As[lk+0][row] = av.x; As[lk+1][row] = av.y;
            As[lk+2][row] = av.z; As[lk+3][row] = av.w;
            float4 bv = *(const float4*)&W[(n0 + row) * K + kt + lk];
            Bs[lk+0][row] = bv.x; Bs[lk+1][row] = bv.y;
            Bs[lk+2][row] = bv.z; Bs[lk+3][row] = bv.w;
        }
        __syncthreads();
        #pragma unroll
        for (int k = 0; k < 16; k++) {
            ulonglong2 a01 = *(const ulonglong2*)&As[k][ty*8];
            ulonglong2 a23 = *(const ulonglong2*)&As[k][ty*8 + 4];
            unsigned long long ap[4] = {a01.x, a01.y, a23.x, a23.y};
            float4 b0 = *(const float4*)&Bs[k][tx*8];
            float4 b1 = *(const float4*)&Bs[k][tx*8 + 4];
            unsigned long long bd[8] = {fdup2(b0.x), fdup2(b0.y), fdup2(b0.z), fdup2(b0.w),
                                        fdup2(b1.x), fdup2(b1.y), fdup2(b1.z), fdup2(b1.w)};
            #pragma unroll
            for (int i = 0; i < 4; i++)
                #pragma unroll
                for (int j = 0; j < 8; j++)
                    acc[i][j] = ffma2(ap[i], bd[j], acc[i][j]);
        }
        __syncthreads();
    }

    #pragma unroll
    for (int i = 0; i < 4; i++) {
        const int m = m0 + ty*8 + i*2;   // pair covers rows m, m+1
        #pragma unroll
        for (int j = 0; j < 8; j++) {
            const int n = n0 + tx*8 + j;
            float2 v = funpack2(acc[i][j]);
            const float bb = bias[n];
            const float v0 = v.x + bb, v1 = v.y + bb;
            if (MODE == 1) {
                out[m * N + n]       = v0;
                out[(m + 1) * N + n] = v1;
            } else {
                const int which = n >> 10, r = n & 1023;
                const int h = r >> 6, d = r & 63;
                float* dst = (which == 0) ? g_Q : (which == 1) ? g_K : g_V;
                const int b = m >> 11, s = m & 2047;  // 128-row tiles never cross batch
                const int off = ((b * NH + h) * SEQ + s) * HD + d;
                dst[off]      = v0;
                dst[off + HD] = v1;   // row m+1 -> s+1
            }
        }
    }
}

// ---------------- RoPE table: fp64-exact, rounded to fp32 ----------------
__global__ void rope_table_kernel() {
    const int idx = blockIdx.x * blockDim.x + threadIdx.x;  // 65536
    const int d = idx & 31, s = idx >> 5;
    const double inv = exp(-((double)d / 32.0) * log(10000.0));
    const float ang = (float)s * (float)inv;   // fp32 mult matches reference
    g_cos[idx] = (float)cos((double)ang);
    g_sin[idx] = (float)sin((double)ang);
}

// ---------------- RoPE apply (in-place on g_Q, g_K) ----------------
__global__ __launch_bounds__(256) void rope_kernel() {
    const int idx = blockIdx.x * 256 + threadIdx.x;  // BSZ*NH*SEQ*32 = 4194304
    const int d  = idx & 31;
    const int s  = (idx >> 5) & 2047;
    const int bh = idx >> 16;
    const int base = (bh * SEQ + s) * HD + d;
    const float c  = g_cos[(s << 5) + d];
    const float sn = g_sin[(s << 5) + d];
    const float q1 = g_Q[base], q2 = g_Q[base + 32];
    g_Q[base]      = q1 * c - q2 * sn;
    g_Q[base + 32] = q2 * c + q1 * sn;
    const float k1 = g_K[base], k2 = g_K[base + 32];
    g_K[base]      = k1 * c - k2 * sn;
    g_K[base + 32] = k2 * c + k1 * sn;
}

// ---------------- Flash attention (fp32, FFMA2 matmuls) ----------------
// grid (32 q-tiles, 64 bh), 256 threads. 64x64 tiles, hd=64.
__global__ __launch_bounds__(256)
void attn_kernel()
{
    __shared__ float Qs[64][64];   // [m][d], pre-scaled
    __shared__ float KP[64][64];   // K transposed [d][c]; reused as P [m][c]
    __shared__ float Vs[64][64];   // [c][d]

    const int tid = threadIdx.x;
    const int qt  = blockIdx.x;
    const int bh  = blockIdx.y;
    const int qbase = (bh * SEQ + qt * 64) * HD;
    const int kbase = bh * SEQ * HD;

    const int lr = tid >> 4;          // 0..15
    const int lc = (tid & 15) * 4;

    #pragma unroll
    for (int it = 0; it < 4; it++) {
        const int row = lr + it * 16;
        float4 v = *(const float4*)&g_Q[qbase + row * 64 + lc];
        v.x *= 0.125f; v.y *= 0.125f; v.z *= 0.125f; v.w *= 0.125f;
        *(float4*)&Qs[row][lc] = v;
    }

    const int ty = tid >> 3;          // 0..31, rows ty*2..+1
    const int tx = tid & 7;           // 0..7, cols tx*8..+7
    const int r0 = ty * 2;
    const int c0 = tx * 8;

    float mrow0 = -INFINITY, mrow1 = -INFINITY;
    float lrow0 = 0.f, lrow1 = 0.f;
    unsigned long long oacc[2][4];
    #pragma unroll
    for (int i = 0; i < 2; i++)
        #pragma unroll
        for (int j = 0; j < 4; j++) oacc[i][j] = 0ull;

    for (int t = 0; t < 32; t++) {
        __syncthreads();   // previous-iter KP/Vs reads done (also covers Qs fill at t=0)
        #pragma unroll
        for (int it = 0; it < 4; it++) {
            const int row = lr + it * 16;
            float4 kv = *(const float4*)&g_K[kbase + (t * 64 + row) * 64 + lc];
            KP[lc+0][row] = kv.x; KP[lc+1][row] = kv.y;
            KP[lc+2][row] = kv.z; KP[lc+3][row] = kv.w;
            *(float4*)&Vs[row][lc] = *(const float4*)&g_V[kbase + (t * 64 + row) * 64 + lc];
        }
        __syncthreads();

        // S = Qs @ K^T  (rows r0..r0+1, key cols c0..c0+7, packed along keys)
        unsigned long long sacc[2][4];
        #pragma unroll
        for (int i = 0; i < 2; i++)
            #pragma unroll
            for (int j = 0; j < 4; j++) sacc[i][j] = 0ull;

        #pragma unroll 16
        for (int d = 0; d < 64; d++) {
            ulonglong2 k01 = *(const ulonglong2*)&KP[d][c0];
            ulonglong2 k23 = *(const ulonglong2*)&KP[d][c0 + 4];
            unsigned long long q0 = fdup2(Qs[r0][d]);
            unsigned long long q1 = fdup2(Qs[r0 + 1][d]);
            sacc[0][0] = ffma2(q0, k01.x, sacc[0][0]);
            sacc[0][1] = ffma2(q0, k01.y, sacc[0][1]);
            sacc[0][2] = ffma2(q0, k23.x, sacc[0][2]);
            sacc[0][3] = ffma2(q0, k23.y, sacc[0][3]);
            sacc[1][0] = ffma2(q1, k01.x, sacc[1][0]);
            sacc[1][1] = ffma2(q1, k01.y, sacc[1][1]);
            sacc[1][2] = ffma2(q1, k23.x, sacc[1][2]);
            sacc[1][3] = ffma2(q1, k23.y, sacc[1][3]);
        }

        // online softmax (row stats across the 8 threads of a ty-group)
        float p[2][8];
        #pragma unroll
        for (int i = 0; i < 2; i++) {
            float sv[8];
            float2 u;
            u = funpack2(sacc[i][0]); sv[0] = u.x; sv[1] = u.y;
            u = funpack2(sacc[i][1]); sv[2] = u.x; sv[3] = u.y;
            u = funpack2(sacc[i][2]); sv[4] = u.x; sv[5] = u.y;
            u = funpack2(sacc[i][3]); sv[6] = u.x; sv[7] = u.y;
            float rmax = sv[0];
            #pragma unroll
            for (int j = 1; j < 8; j++) rmax = fmaxf(rmax, sv[j]);
            #pragma unroll
            for (int o = 4; o > 0; o >>= 1)
                rmax = fmaxf(rmax, __shfl_xor_sync(0xffffffffu, rmax, o, 8));
            const float mold = (i == 0) ? mrow0 : mrow1;
            const float mnew = fmaxf(mold, rmax);
            const float corr = __expf(mold - mnew);
            float rsum = 0.f;
            #pragma unroll
            for (int j = 0; j < 8; j++) { p[i][j] = __expf(sv[j] - mnew); rsum += p[i][j]; }
            #pragma unroll
            for (int o = 4; o > 0; o >>= 1)
                rsum += __shfl_xor_sync(0xffffffffu, rsum, o, 8);
            if (i == 0) { mrow0 = mnew; lrow0 = lrow0 * corr + rsum; }
            else        { mrow1 = mnew; lrow1 = lrow1 * corr + rsum; }
            const unsigned long long cd = fdup2(corr);
            oacc[i][0] = fmul2(oacc[i][0], cd);
            oacc[i][1] = fmul2(oacc[i][1], cd);
            oacc[i][2] = fmul2(oacc[i][2], cd);
            oacc[i][3] = fmul2(oacc[i][3], cd);
        }

        __syncthreads();   // all KP reads done -> reuse as P buffer
        *(float4*)&KP[r0][c0]       = make_float4(p[0][0], p[0][1], p[0][2], p[0][3]);
        *(float4*)&KP[r0][c0 + 4]   = make_float4(p[0][4], p[0][5], p[0][6], p[0][7]);
        *(float4*)&KP[r0+1][c0]     = make_float4(p[1][0], p[1][1], p[1][2], p[1][3]);
        *(float4*)&KP[r0+1][c0 + 4] = make_float4(p[1][4], p[1][5], p[1][6], p[1][7]);
        __syncthreads();

        // O += P @ V  (rows r0..r0+1, d cols c0..c0+7, packed along d)
        #pragma unroll 16
        for (int c = 0; c < 64; c++) {
            ulonglong2 v01 = *(const ulonglong2*)&Vs[c][c0];
            ulonglong2 v23 = *(const ulonglong2*)&Vs[c][c0 + 4];
            unsigned long long p0 = fdup2(KP[r0][c]);
            unsigned long long p1 = fdup2(KP[r0 + 1][c]);
            oacc[0][0] = ffma2(p0, v01.x, oacc[0][0]);
            oacc[0][1] = ffma2(p0, v01.y, oacc[0][1]);
            oacc[0][2] = ffma2(p0, v23.x, oacc[0][2]);
            oacc[0][3] = ffma2(p0, v23.y, oacc[0][3]);
            oacc[1][0] = ffma2(p1, v01.x, oacc[1][0]);
            oacc[1][1] = ffma2(p1, v01.y, oacc[1][1]);
            oacc[1][2] = ffma2(p1, v23.x, oacc[1][2]);
            oacc[1][3] = ffma2(p1, v23.y, oacc[1][3]);
        }
    }

    // finalize: g_AO[b][s][h*64+d]
    const int b = bh >> 4, h = bh & 15;
    const int obase = (b * SEQ + qt * 64 + r0) * EMB + h * 64 + c0;
    const float inv0 = 1.0f / lrow0;
    const float inv1 = 1.0f / lrow1;
    float2 u;
    float o[8];
    u = funpack2(oacc[0][0]); o[0] = u.x * inv0; o[1] = u.y * inv0;
    u = funpack2(oacc[0][1]); o[2] = u.x * inv0; o[3] = u.y * inv0;
    u = funpack2(oacc[0][2]); o[4] = u.x * inv0; o[5] = u.y * inv0;
    u = funpack2(oacc[0][3]); o[6] = u.x * inv0; o[7] = u.y * inv0;
    *(float4*)&g_AO[obase]     = make_float4(o[0], o[1], o[2], o[3]);
    *(float4*)&g_AO[obase + 4] = make_float4(o[4], o[5], o[6], o[7]);
    u = funpack2(oacc[1][0]); o[0] = u.x * inv1; o[1] = u.y * inv1;
    u = funpack2(oacc[1][1]); o[2] = u.x * inv1; o[3] = u.y * inv1;
    u = funpack2(oacc[1][2]); o[4] = u.x * inv1; o[5] = u.y * inv1;
    u = funpack2(oacc[1][3]); o[6] = u.x * inv1; o[7] = u.y * inv1;
    *(float4*)&g_AO[obase + EMB]     = make_float4(o[0], o[1], o[2], o[3]);
    *(float4*)&g_AO[obase + EMB + 4] = make_float4(o[4], o[5], o[6], o[7]);
}

// ---------------- launch ----------------
extern "C" void kernel_launch(void* const* d_in, const int* in_sizes, int n_in,
                              void* d_out, int out_size)
{
    const float* hidden = (const float*)d_in[0];
    const float* qkv_w  = (const float*)d_in[1];
    const float* qkv_b  = (const float*)d_in[2];
    const float* proj_w = (const float*)d_in[3];
    const float* proj_b = (const float*)d_in[4];
    float* out = (float*)d_out;

    // 1) QKV projection -> g_Q/g_K/g_V  (M=8192, N=3072, K=1024)
    gemm_kernel<0, 3072><<<dim3(24, 64), 256>>>(hidden, qkv_w, qkv_b, nullptr);

    // 2) RoPE table + apply
    rope_table_kernel<<<256, 256>>>();
    rope_kernel<<<(BSZ*NH*SEQ*32)/256, 256>>>();

    // 3) Attention -> g_AO
    attn_kernel<<<dim3(32, 64), 256>>>();

    // 4) Output projection -> d_out  (M=8192, N=1024, K=1024)
    gemm_kernel<1, 1024><<<dim3(8, 64), 256>>>(nullptr, proj_w, proj_b, out);
}

// round 10
// speedup vs baseline: 4.1208x; 2.5031x over previous
#include <cuda_runtime.h>
#include <cuda_bf16.h>
#include <math.h>
#include <stdint.h>

#define BSZ 4
#define SEQ 2048
#define EMB 1024
#define NH  16
#define HD  64
#define MTOT (BSZ*SEQ)   // 8192

// ---------------- scratch (device globals; no allocation allowed) ----------------
__device__ __align__(16) float g_Q [BSZ*NH*SEQ*HD];
__device__ __align__(16) float g_K [BSZ*NH*SEQ*HD];
__device__ __align__(16) float g_V [BSZ*NH*SEQ*HD];
__device__ __align__(16) float g_AO[BSZ*SEQ*EMB];
__device__ __align__(16) float g_cos[SEQ*32];
__device__ __align__(16) float g_sin[SEQ*32];
__device__ __align__(16) __nv_bfloat16 g_Ahi [MTOT*EMB];
__device__ __align__(16) __nv_bfloat16 g_Alo [MTOT*EMB];
__device__ __align__(16) __nv_bfloat16 g_Whi [3*EMB*EMB];
__device__ __align__(16) __nv_bfloat16 g_Wlo [3*EMB*EMB];
__device__ __align__(16) __nv_bfloat16 g_Phi [EMB*EMB];
__device__ __align__(16) __nv_bfloat16 g_Plo [EMB*EMB];
__device__ __align__(16) __nv_bfloat16 g_AOhi[MTOT*EMB];
__device__ __align__(16) __nv_bfloat16 g_AOlo[MTOT*EMB];

// ---------------- packed f32x2 helpers (FFMA2 pipe) ----------------
__device__ __forceinline__ unsigned long long ffma2(unsigned long long a,
                                                    unsigned long long b,
                                                    unsigned long long c) {
    unsigned long long d;
    asm("fma.rn.f32x2 %0, %1, %2, %3;" : "=l"(d) : "l"(a), "l"(b), "l"(c));
    return d;
}
__device__ __forceinline__ unsigned long long fmul2(unsigned long long a,
                                                    unsigned long long b) {
    unsigned long long d;
    asm("mul.rn.f32x2 %0, %1, %2;" : "=l"(d) : "l"(a), "l"(b));
    return d;
}
__device__ __forceinline__ unsigned long long fdup2(float x) {
    unsigned long long r;
    asm("mov.b64 %0, {%1, %2};" : "=l"(r) : "f"(x), "f"(x));
    return r;
}
__device__ __forceinline__ float2 funpack2(unsigned long long v) {
    float2 f;
    asm("mov.b64 {%0, %1}, %2;" : "=f"(f.x), "=f"(f.y) : "l"(v));
    return f;
}

// ---------------- HMMA: m16n8k16 bf16 -> f32 ----------------
__device__ __forceinline__ void mma16816(float* c, const uint32_t* a,
                                         uint32_t b0, uint32_t b1) {
    asm volatile(
        "mma.sync.aligned.m16n8k16.row.col.f32.bf16.bf16.f32 "
        "{%0,%1,%2,%3}, {%4,%5,%6,%7}, {%8,%9}, {%0,%1,%2,%3};"
        : "+f"(c[0]), "+f"(c[1]), "+f"(c[2]), "+f"(c[3])
        : "r"(a[0]), "r"(a[1]), "r"(a[2]), "r"(a[3]), "r"(b0), "r"(b1));
}

// ---------------- fp32 -> bf16 hi/lo split ----------------
// sel: 0 hidden, 1 qkv_w, 2 proj_w, 3 g_AO
__global__ __launch_bounds__(256) void split_kernel(const float* __restrict__ src_ext, int sel) {
    __nv_bfloat16 *hi, *lo;
    const float* src = src_ext;
    if      (sel == 0) { hi = g_Ahi;  lo = g_Alo;  }
    else if (sel == 1) { hi = g_Whi;  lo = g_Wlo;  }
    else if (sel == 2) { hi = g_Phi;  lo = g_Plo;  }
    else               { hi = g_AOhi; lo = g_AOlo; src = g_AO; }
    const int i = (blockIdx.x * 256 + threadIdx.x) * 4;
    float4 v = *(const float4*)&src[i];
    float f[4] = {v.x, v.y, v.z, v.w};
    __nv_bfloat16 h[4], l[4];
    #pragma unroll
    for (int j = 0; j < 4; j++) {
        h[j] = __float2bfloat16(f[j]);
        l[j] = __float2bfloat16(f[j] - __bfloat162float(h[j]));
    }
    *(__nv_bfloat162*)&hi[i]     = *(__nv_bfloat162*)&h[0];
    *(__nv_bfloat162*)&hi[i + 2] = *(__nv_bfloat162*)&h[2];
    *(__nv_bfloat162*)&lo[i]     = *(__nv_bfloat162*)&l[0];
    *(__nv_bfloat162*)&lo[i + 2] = *(__nv_bfloat162*)&l[2];
}

// ---------------- RoPE table (fp64-exact) ----------------
__global__ void rope_table_kernel() {
    const int idx = blockIdx.x * blockDim.x + threadIdx.x;
    const int d = idx & 31, s = idx >> 5;
    const double inv = exp(-((double)d / 32.0) * log(10000.0));
    const float ang = (float)s * (float)inv;
    g_cos[idx] = (float)cos((double)ang);
    g_sin[idx] = (float)sin((double)ang);
}

// ---------------- HMMA bf16 split-3 GEMM ----------------
// C[M,N] = A[M,1024] @ W[N,1024]^T + bias ; A=Ahi+Alo, W=Whi+Wlo (3 passes)
// MODE 0: QKV -> bias + RoPE + scatter to g_Q/g_K/g_V
// MODE 1: proj -> bias -> out row-major
// CTA: 128x128 tile, 256 threads (8 warps; warp tile 32 rows x 64 cols).
#define GP 72   // smem pitch in bf16
template<int MODE>
__global__ __launch_bounds__(256, 2)
void hmma_gemm(const float* __restrict__ bias, float* __restrict__ out)
{
    extern __shared__ __align__(16) char dynsmem[];
    __nv_bfloat16* sAh = (__nv_bfloat16*)dynsmem;     // [128][GP]
    __nv_bfloat16* sAl = sAh + 128 * GP;
    __nv_bfloat16* sBh = sAl + 128 * GP;
    __nv_bfloat16* sBl = sBh + 128 * GP;

    const int tid = threadIdx.x;
    const int wid = tid >> 5, lane = tid & 31;
    const int n0 = blockIdx.x * 128;
    const int m0 = blockIdx.y * 128;

    const __nv_bfloat16* Ah = ((MODE == 0) ? g_Ahi : g_AOhi) + (size_t)m0 * 1024;
    const __nv_bfloat16* Al = ((MODE == 0) ? g_Alo : g_AOlo) + (size_t)m0 * 1024;
    const __nv_bfloat16* Bh = ((MODE == 0) ? g_Whi : g_Phi) + (size_t)n0 * 1024;
    const __nv_bfloat16* Bl = ((MODE == 0) ? g_Wlo : g_Plo) + (size_t)n0 * 1024;

    const int wm = wid >> 1, wn = wid & 1;
    const int gr = lane >> 2, qc = (lane & 3) * 2;

    float acc[2][8][4];
    #pragma unroll
    for (int mt = 0; mt < 2; mt++)
        #pragma unroll
        for (int nt = 0; nt < 8; nt++)
            #pragma unroll
            for (int e = 0; e < 4; e++) acc[mt][nt][e] = 0.f;

    const int lrow = tid >> 1;             // 0..127
    const int ub = (tid & 1) * 4;          // uint4 sub-offset within row-chunk

    for (int c = 0; c < 16; c++) {
        __syncthreads();
        // load 128x64 bf16 chunk of each of the 4 operands (uint4 = 8 bf16)
        {
            const int gidx = lrow * 128 + c * 8;   // uint4 index base in gmem row
            const __nv_bfloat16* gs[4] = {Ah, Al, Bh, Bl};
            __nv_bfloat16* ss[4] = {sAh, sAl, sBh, sBl};
            #pragma unroll
            for (int t = 0; t < 4; t++) {
                const uint4* g = (const uint4*)gs[t] + gidx + ub;
                __nv_bfloat16* sp = ss[t] + lrow * GP + ub * 8;
                #pragma unroll
                for (int j = 0; j < 4; j++)
                    *(uint4*)(sp + j * 8) = g[j];
            }
        }
        __syncthreads();

        const __nv_bfloat16* pAh = sAh + (wm * 32) * GP;
        const __nv_bfloat16* pAl = sAl + (wm * 32) * GP;
        const __nv_bfloat16* pBh = sBh + (wn * 64) * GP;
        const __nv_bfloat16* pBl = sBl + (wn * 64) * GP;

        #pragma unroll
        for (int kk = 0; kk < 64; kk += 16) {
            uint32_t ah[2][4], al[2][4];
            #pragma unroll
            for (int mt = 0; mt < 2; mt++) {
                const __nv_bfloat16* a0 = pAh + (mt * 16 + gr) * GP + kk + qc;
                ah[mt][0] = *(const uint32_t*)(a0);
                ah[mt][1] = *(const uint32_t*)(a0 + 8 * GP);
                ah[mt][2] = *(const uint32_t*)(a0 + 8);
                ah[mt][3] = *(const uint32_t*)(a0 + 8 * GP + 8);
                const __nv_bfloat16* a1 = pAl + (mt * 16 + gr) * GP + kk + qc;
                al[mt][0] = *(const uint32_t*)(a1);
                al[mt][1] = *(const uint32_t*)(a1 + 8 * GP);
                al[mt][2] = *(const uint32_t*)(a1 + 8);
                al[mt][3] = *(const uint32_t*)(a1 + 8 * GP + 8);
            }
            #pragma unroll
            for (int nt = 0; nt < 8; nt++) {
                const __nv_bfloat16* b0 = pBh + (nt * 8 + gr) * GP + kk + qc;
                const uint32_t bh0 = *(const uint32_t*)(b0);
                const uint32_t bh1 = *(const uint32_t*)(b0 + 8);
                const __nv_bfloat16* b1 = pBl + (nt * 8 + gr) * GP + kk + qc;
                const uint32_t bl0 = *(const uint32_t*)(b1);
                const uint32_t bl1 = *(const uint32_t*)(b1 + 8);
                #pragma unroll
                for (int mt = 0; mt < 2; mt++) {
                    mma16816(acc[mt][nt], ah[mt], bh0, bh1);
                    mma16816(acc[mt][nt], ah[mt], bl0, bl1);
                    mma16816(acc[mt][nt], al[mt], bh0, bh1);
                }
            }
        }
    }

    // epilogue: thread owns rows {gr, gr+8} per mt-tile, cols nt*8+qc..+1 in warp's 64-col span
    const int cb = n0 + wn * 64;
    #pragma unroll
    for (int mt = 0; mt < 2; mt++) {
        #pragma unroll
        for (int rr = 0; rr < 2; rr++) {
            const int mrow = m0 + wm * 32 + mt * 16 + gr + rr * 8;
            float v[16];
            #pragma unroll
            for (int nt = 0; nt < 8; nt++) {
                v[nt * 2 + 0] = acc[mt][nt][rr * 2 + 0] + bias[cb + nt * 8 + qc + 0];
                v[nt * 2 + 1] = acc[mt][nt][rr * 2 + 1] + bias[cb + nt * 8 + qc + 1];
            }
            if (MODE == 0) {
                const int which = cb >> 10;
                const int h = (cb & 1023) >> 6;
                const int b = mrow >> 11, s = mrow & 2047;
                float* dst = (which == 0) ? g_Q : (which == 1) ? g_K : g_V;
                if (which < 2) {
                    #pragma unroll
                    for (int nt = 0; nt < 4; nt++)
                        #pragma unroll
                        for (int e = 0; e < 2; e++) {
                            const int d = nt * 8 + qc + e;
                            const float cc = g_cos[(s << 5) + d];
                            const float sn = g_sin[(s << 5) + d];
                            const float x = v[nt * 2 + e], y = v[(nt + 4) * 2 + e];
                            v[nt * 2 + e]       = x * cc - y * sn;
                            v[(nt + 4) * 2 + e] = y * cc + x * sn;
                        }
                }
                float* o = dst + ((size_t)((b * NH + h) * SEQ + s)) * HD;
                #pragma unroll
                for (int nt = 0; nt < 8; nt++)
                    *(float2*)&o[nt * 8 + qc] = make_float2(v[nt * 2], v[nt * 2 + 1]);
            } else {
                float* o = out + (size_t)mrow * 1024 + cb;
                #pragma unroll
                for (int nt = 0; nt < 8; nt++)
                    *(float2*)&o[nt * 8 + qc] = make_float2(v[nt * 2], v[nt * 2 + 1]);
            }
        }
    }
}

// ---------------- Flash attention v2 (FFMA2, 8x8 per thread) ----------------
// grid (16 q-tiles of 128 rows, 64 bh), 128 threads. Thread (ty,tx): rows ty+16i, cols tx*8..+7.
#define QP 68   // padded pitch (floats) for Qs/Ps and Vs
__global__ __launch_bounds__(128, 2)
void attn2_kernel()
{
    extern __shared__ __align__(16) char dynsmem[];
    float* Qs = (float*)dynsmem;            // [128][QP]
    float* Ps = Qs + 128 * QP;              // [128][QP]
    float* Kt = Ps + 128 * QP;              // [64][64]  (d-major)
    float* Vs = Kt + 64 * 64;               // [64][QP]  (c-major, padded)

    const int tid = threadIdx.x;
    const int qt = blockIdx.x, bh = blockIdx.y;
    const size_t qbase = ((size_t)bh * SEQ + qt * 128) * HD;
    const size_t kbase = (size_t)bh * SEQ * HD;

    // load Q (pre-scaled): thread = one row
    #pragma unroll
    for (int u = 0; u < 16; u++) {
        float4 v = *(const float4*)&g_Q[qbase + tid * 64 + u * 4];
        v.x *= 0.125f; v.y *= 0.125f; v.z *= 0.125f; v.w *= 0.125f;
        *(float4*)&Qs[tid * QP + u * 4] = v;
    }

    const int ty = tid >> 3, tx = tid & 7;
    const int c0 = tx * 8;
    float mrow[8], lrow[8];
    unsigned long long oacc[8][4];
    #pragma unroll
    for (int i = 0; i < 8; i++) {
        mrow[i] = -INFINITY; lrow[i] = 0.f;
        #pragma unroll
        for (int j = 0; j < 4; j++) oacc[i][j] = 0ull;
    }

    const int lrow_kv = tid & 63;         // K/V row for loading
    const int sel = tid >> 6;             // threads 0-63: K, 64-127: V

    for (int t = 0; t < 32; t++) {
        __syncthreads();
        if (sel == 0) {
            #pragma unroll
            for (int u = 0; u < 16; u++) {
                float4 kv = *(const float4*)&g_K[kbase + (t * 64 + lrow_kv) * 64 + u * 4];
                Kt[(u * 4 + 0) * 64 + lrow_kv] = kv.x;
                Kt[(u * 4 + 1) * 64 + lrow_kv] = kv.y;
                Kt[(u * 4 + 2) * 64 + lrow_kv] = kv.z;
                Kt[(u * 4 + 3) * 64 + lrow_kv] = kv.w;
            }
        } else {
            #pragma unroll
            for (int u = 0; u < 16; u++)
                *(float4*)&Vs[lrow_kv * QP + u * 4] =
                    *(const float4*)&g_V[kbase + (t * 64 + lrow_kv) * 64 + u * 4];
        }
        __syncthreads();

        // S = Q K^T : 8 rows x 8 key-cols, keys packed
        unsigned long long sacc[8][4];
        #pragma unroll
        for (int i = 0; i < 8; i++)
            #pragma unroll
            for (int j = 0; j < 4; j++) sacc[i][j] = 0ull;

        for (int db = 0; db < 64; db += 4) {
            float q[8][4];
            #pragma unroll
            for (int i = 0; i < 8; i++)
                *(float4*)q[i] = *(const float4*)&Qs[(ty + 16 * i) * QP + db];
            #pragma unroll
            for (int dj = 0; dj < 4; dj++) {
                const float* kr = &Kt[(db + dj) * 64 + c0];
                ulonglong2 k01 = *(const ulonglong2*)kr;
                ulonglong2 k23 = *(const ulonglong2*)(kr + 4);
                #pragma unroll
                for (int i = 0; i < 8; i++) {
                    const unsigned long long qd = fdup2(q[i][dj]);
                    sacc[i][0] = ffma2(qd, k01.x, sacc[i][0]);
                    sacc[i][1] = ffma2(qd, k01.y, sacc[i][1]);
                    sacc[i][2] = ffma2(qd, k23.x, sacc[i][2]);
                    sacc[i][3] = ffma2(qd, k23.y, sacc[i][3]);
                }
            }
        }

        // online softmax per row; write P
        #pragma unroll
        for (int i = 0; i < 8; i++) {
            float sv[8];
            float2 u;
            u = funpack2(sacc[i][0]); sv[0] = u.x; sv[1] = u.y;
            u = funpack2(sacc[i][1]); sv[2] = u.x; sv[3] = u.y;
            u = funpack2(sacc[i][2]); sv[4] = u.x; sv[5] = u.y;
            u = funpack2(sacc[i][3]); sv[6] = u.x; sv[7] = u.y;
            float rmax = sv[0];
            #pragma unroll
            for (int j = 1; j < 8; j++) rmax = fmaxf(rmax, sv[j]);
            #pragma unroll
            for (int o = 4; o > 0; o >>= 1)
                rmax = fmaxf(rmax, __shfl_xor_sync(0xffffffffu, rmax, o, 8));
            const float mnew = fmaxf(mrow[i], rmax);
            const float corr = __expf(mrow[i] - mnew);
            float p[8], rsum = 0.f;
            #pragma unroll
            for (int j = 0; j < 8; j++) { p[j] = __expf(sv[j] - mnew); rsum += p[j]; }
            #pragma unroll
            for (int o = 4; o > 0; o >>= 1)
                rsum += __shfl_xor_sync(0xffffffffu, rsum, o, 8);
            mrow[i] = mnew;
            lrow[i] = lrow[i] * corr + rsum;
            const unsigned long long cd = fdup2(corr);
            #pragma unroll
            for (int j = 0; j < 4; j++) oacc[i][j] = fmul2(oacc[i][j], cd);
            float* pr = &Ps[(ty + 16 * i) * QP + c0];
            *(float4*)pr = make_float4(p[0], p[1], p[2], p[3]);
            *(float4*)(pr + 4) = make_float4(p[4], p[5], p[6], p[7]);
        }
        __syncthreads();

        // O += P V : d-cols packed
        for (int cb = 0; cb < 64; cb += 4) {
            float pb[8][4];
            #pragma unroll
            for (int i = 0; i < 8; i++)
                *(float4*)pb[i] = *(const float4*)&Ps[(ty + 16 * i) * QP + cb];
            #pragma unroll
            for (int cj = 0; cj < 4; cj++) {
                const float* vr = &Vs[(cb + cj) * QP + c0];
                ulonglong2 v01 = *(const ulonglong2*)vr;
                ulonglong2 v23 = *(const ulonglong2*)(vr + 4);
                #pragma unroll
                for (int i = 0; i < 8; i++) {
                    const unsigned long long pd = fdup2(pb[i][cj]);
                    oacc[i][0] = ffma2(pd, v01.x, oacc[i][0]);
                    oacc[i][1] = ffma2(pd, v01.y, oacc[i][1]);
                    oacc[i][2] = ffma2(pd, v23.x, oacc[i][2]);
                    oacc[i][3] = ffma2(pd, v23.y, oacc[i][3]);
                }
            }
        }
    }

    // finalize -> g_AO[b][s][h*64+d]
    const int b = bh >> 4, h = bh & 15;
    #pragma unroll
    for (int i = 0; i < 8; i++) {
        const float inv = 1.0f / lrow[i];
        const int row = qt * 128 + ty + 16 * i;
        float* o = &g_AO[((size_t)b * SEQ + row) * EMB + h * 64 + c0];
        float ov[8];
        float2 u;
        u = funpack2(oacc[i][0]); ov[0] = u.x * inv; ov[1] = u.y * inv;
        u = funpack2(oacc[i][1]); ov[2] = u.x * inv; ov[3] = u.y * inv;
        u = funpack2(oacc[i][2]); ov[4] = u.x * inv; ov[5] = u.y * inv;
        u = funpack2(oacc[i][3]); ov[6] = u.x * inv; ov[7] = u.y * inv;
        *(float4*)o = make_float4(ov[0], ov[1], ov[2], ov[3]);
        *(float4*)(o + 4) = make_float4(ov[4], ov[5], ov[6], ov[7]);
    }
}

// ---------------- launch ----------------
extern "C" void kernel_launch(void* const* d_in, const int* in_sizes, int n_in,
                              void* d_out, int out_size)
{
    const float* hidden = (const float*)d_in[0];
    const float* qkv_w  = (const float*)d_in[1];
    const float* qkv_b  = (const float*)d_in[2];
    const float* proj_w = (const float*)d_in[3];
    const float* proj_b = (const float*)d_in[4];
    float* out = (float*)d_out;

    const int GEMM_SMEM = 4 * 128 * GP * 2;                      // 73728
    const int ATTN_SMEM = (2 * 128 * QP + 64 * 64 + 64 * QP) * 4; // 103424
    cudaFuncSetAttribute(hmma_gemm<0>, cudaFuncAttributeMaxDynamicSharedMemorySize, GEMM_SMEM);
    cudaFuncSetAttribute(hmma_gemm<1>, cudaFuncAttributeMaxDynamicSharedMemorySize, GEMM_SMEM);
    cudaFuncSetAttribute(attn2_kernel, cudaFuncAttributeMaxDynamicSharedMemorySize, ATTN_SMEM);

    // RoPE table + input splits
    rope_table_kernel<<<256, 256>>>();
    split_kernel<<<8192, 256>>>(hidden, 0);
    split_kernel<<<3072, 256>>>(qkv_w, 1);
    split_kernel<<<1024, 256>>>(proj_w, 2);

    // QKV projection + bias + RoPE + scatter (HMMA split-3)
    hmma_gemm<0><<<dim3(24, 64), 256, GEMM_SMEM>>>(qkv_b, nullptr);

    // attention -> g_AO
    attn2_kernel<<<dim3(16, 64), 128, ATTN_SMEM>>>();

    // split AO, output projection (HMMA split-3)
    split_kernel<<<8192, 256>>>(nullptr, 3);
    hmma_gemm<1><<<dim3(8, 64), 256, GEMM_SMEM>>>(proj_b, out);
}

// round 14
// speedup vs baseline: 7.4622x; 1.8109x over previous
#include <cuda_runtime.h>
#include <cuda_bf16.h>
#include <math.h>
#include <stdint.h>

#define BSZ 4
#define SEQ 2048
#define EMB 1024
#define NH  16
#define HD  64
#define MTOT (BSZ*SEQ)   // 8192

// ---------------- scratch (device globals; no allocation allowed) ----------------
__device__ __align__(16) float g_cos[SEQ*32];
__device__ __align__(16) float g_sin[SEQ*32];
// GEMM operands (fp32 -> bf16 hi/lo splits)
__device__ __align__(16) __nv_bfloat16 g_Ahi [MTOT*EMB];
__device__ __align__(16) __nv_bfloat16 g_Alo [MTOT*EMB];
__device__ __align__(16) __nv_bfloat16 g_Whi [3*EMB*EMB];
__device__ __align__(16) __nv_bfloat16 g_Wlo [3*EMB*EMB];
__device__ __align__(16) __nv_bfloat16 g_Phi [EMB*EMB];
__device__ __align__(16) __nv_bfloat16 g_Plo [EMB*EMB];
// attention operands, bf16 hi/lo, written by QKV GEMM epilogue
__device__ __align__(16) __nv_bfloat16 g_Qhi [BSZ*NH*SEQ*HD];  // [bh][s][d], pre-scaled by 0.125
__device__ __align__(16) __nv_bfloat16 g_Qlo [BSZ*NH*SEQ*HD];
__device__ __align__(16) __nv_bfloat16 g_Khi [BSZ*NH*SEQ*HD];  // [bh][s][d]
__device__ __align__(16) __nv_bfloat16 g_Klo [BSZ*NH*SEQ*HD];
__device__ __align__(16) __nv_bfloat16 g_VThi[BSZ*NH*HD*SEQ];  // [bh][d][s]  (transposed)
__device__ __align__(16) __nv_bfloat16 g_VTlo[BSZ*NH*HD*SEQ];
// attention output, bf16 hi/lo (input of proj GEMM)
__device__ __align__(16) __nv_bfloat16 g_AOhi[MTOT*EMB];
__device__ __align__(16) __nv_bfloat16 g_AOlo[MTOT*EMB];

// ---------------- helpers ----------------
__device__ __forceinline__ uint32_t smem_u32(const void* p) {
    uint32_t a;
    asm("{ .reg .u64 t; cvta.to.shared.u64 t, %1; cvt.u32.u64 %0, t; }" : "=r"(a) : "l"(p));
    return a;
}
__device__ __forceinline__ uint32_t packbf(float x, float y) {
    uint16_t lx = __bfloat16_as_ushort(__float2bfloat16(x));
    uint16_t ly = __bfloat16_as_ushort(__float2bfloat16(y));
    return (uint32_t)lx | ((uint32_t)ly << 16);
}
__device__ __forceinline__ float bf16lo(float x) {
    return x - __bfloat162float(__float2bfloat16(x));
}
// HMMA m16n8k16 bf16 -> f32
__device__ __forceinline__ void mma16816(float* c, const uint32_t* a,
                                         uint32_t b0, uint32_t b1) {
    asm volatile(
        "mma.sync.aligned.m16n8k16.row.col.f32.bf16.bf16.f32 "
        "{%0,%1,%2,%3}, {%4,%5,%6,%7}, {%8,%9}, {%0,%1,%2,%3};"
        : "+f"(c[0]), "+f"(c[1]), "+f"(c[2]), "+f"(c[3])
        : "r"(a[0]), "r"(a[1]), "r"(a[2]), "r"(a[3]), "r"(b0), "r"(b1));
}

// ---------------- fp32 -> bf16 hi/lo split (GEMM inputs) ----------------
__global__ __launch_bounds__(256) void split_kernel(const float* __restrict__ src, int sel) {
    __nv_bfloat16 *hi, *lo;
    if      (sel == 0) { hi = g_Ahi; lo = g_Alo; }
    else if (sel == 1) { hi = g_Whi; lo = g_Wlo; }
    else               { hi = g_Phi; lo = g_Plo; }
    const int i = (blockIdx.x * 256 + threadIdx.x) * 4;
    float4 v = *(const float4*)&src[i];
    float f[4] = {v.x, v.y, v.z, v.w};
    #pragma unroll
    for (int j = 0; j < 4; j += 2) {
        *(uint32_t*)&hi[i + j] = packbf(f[j], f[j + 1]);
        *(uint32_t*)&lo[i + j] = packbf(bf16lo(f[j]), bf16lo(f[j + 1]));
    }
}

// ---------------- RoPE table (fp64-exact) ----------------
__global__ void rope_table_kernel() {
    const int idx = blockIdx.x * blockDim.x + threadIdx.x;
    const int d = idx & 31, s = idx >> 5;
    const double inv = exp(-((double)d / 32.0) * log(10000.0));
    const float ang = (float)s * (float)inv;
    g_cos[idx] = (float)cos((double)ang);
    g_sin[idx] = (float)sin((double)ang);
}

// ---------------- HMMA bf16 split-3 GEMM ----------------
// MODE 0: QKV -> bias + RoPE + bf16-split scatter (Q scaled 0.125; V transposed)
// MODE 1: proj -> bias -> out row-major fp32
#define GP 72
template<int MODE>
__global__ __launch_bounds__(256, 2)
void hmma_gemm(const float* __restrict__ bias, float* __restrict__ out)
{
    extern __shared__ __align__(16) char dynsmem[];
    __nv_bfloat16* sAh = (__nv_bfloat16*)dynsmem;     // [128][GP]
    __nv_bfloat16* sAl = sAh + 128 * GP;
    __nv_bfloat16* sBh = sAl + 128 * GP;
    __nv_bfloat16* sBl = sBh + 128 * GP;

    const int tid = threadIdx.x;
    const int wid = tid >> 5, lane = tid & 31;
    const int n0 = blockIdx.x * 128;
    const int m0 = blockIdx.y * 128;

    const __nv_bfloat16* Ah = ((MODE == 0) ? g_Ahi : g_AOhi) + (size_t)m0 * 1024;
    const __nv_bfloat16* Al = ((MODE == 0) ? g_Alo : g_AOlo) + (size_t)m0 * 1024;
    const __nv_bfloat16* Bh = ((MODE == 0) ? g_Whi : g_Phi) + (size_t)n0 * 1024;
    const __nv_bfloat16* Bl = ((MODE == 0) ? g_Wlo : g_Plo) + (size_t)n0 * 1024;

    const int wm = wid >> 1, wn = wid & 1;
    const int gr = lane >> 2, qc = (lane & 3) * 2;

    float acc[2][8][4];
    #pragma unroll
    for (int mt = 0; mt < 2; mt++)
        #pragma unroll
        for (int nt = 0; nt < 8; nt++)
            #pragma unroll
            for (int e = 0; e < 4; e++) acc[mt][nt][e] = 0.f;

    const int lrow = tid >> 1;
    const int ub = (tid & 1) * 4;

    for (int c = 0; c < 16; c++) {
        __syncthreads();
        {
            const int gidx = lrow * 128 + c * 8;
            const __nv_bfloat16* gs[4] = {Ah, Al, Bh, Bl};
            __nv_bfloat16* ss[4] = {sAh, sAl, sBh, sBl};
            #pragma unroll
            for (int t = 0; t < 4; t++) {
                const uint4* g = (const uint4*)gs[t] + gidx + ub;
                __nv_bfloat16* sp = ss[t] + lrow * GP + ub * 8;
                #pragma unroll
                for (int j = 0; j < 4; j++)
                    *(uint4*)(sp + j * 8) = g[j];
            }
        }
        __syncthreads();

        const __nv_bfloat16* pAh = sAh + (wm * 32) * GP;
        const __nv_bfloat16* pAl = sAl + (wm * 32) * GP;
        const __nv_bfloat16* pBh = sBh + (wn * 64) * GP;
        const __nv_bfloat16* pBl = sBl + (wn * 64) * GP;

        #pragma unroll
        for (int kk = 0; kk < 64; kk += 16) {
            uint32_t ah[2][4], al[2][4];
            #pragma unroll
            for (int mt = 0; mt < 2; mt++) {
                const __nv_bfloat16* a0 = pAh + (mt * 16 + gr) * GP + kk + qc;
                ah[mt][0] = *(const uint32_t*)(a0);
                ah[mt][1] = *(const uint32_t*)(a0 + 8 * GP);
                ah[mt][2] = *(const uint32_t*)(a0 + 8);
                ah[mt][3] = *(const uint32_t*)(a0 + 8 * GP + 8);
                const __nv_bfloat16* a1 = pAl + (mt * 16 + gr) * GP + kk + qc;
                al[mt][0] = *(const uint32_t*)(a1);
                al[mt][1] = *(const uint32_t*)(a1 + 8 * GP);
                al[mt][2] = *(const uint32_t*)(a1 + 8);
                al[mt][3] = *(const uint32_t*)(a1 + 8 * GP + 8);
            }
            #pragma unroll
            for (int nt = 0; nt < 8; nt++) {
                const __nv_bfloat16* b0 = pBh + (nt * 8 + gr) * GP + kk + qc;
                const uint32_t bh0 = *(const uint32_t*)(b0);
                const uint32_t bh1 = *(const uint32_t*)(b0 + 8);
                const __nv_bfloat16* b1 = pBl + (nt * 8 + gr) * GP + kk + qc;
                const uint32_t bl0 = *(const uint32_t*)(b1);
                const uint32_t bl1 = *(const uint32_t*)(b1 + 8);
                #pragma unroll
                for (int mt = 0; mt < 2; mt++) {
                    mma16816(acc[mt][nt], ah[mt], bh0, bh1);
                    mma16816(acc[mt][nt], ah[mt], bl0, bl1);
                    mma16816(acc[mt][nt], al[mt], bh0, bh1);
                }
            }
        }
    }

    const int cb = n0 + wn * 64;
    #pragma unroll
    for (int mt = 0; mt < 2; mt++) {
        #pragma unroll
        for (int rr = 0; rr < 2; rr++) {
            const int mrow = m0 + wm * 32 + mt * 16 + gr + rr * 8;
            float v[16];
            #pragma unroll
            for (int nt = 0; nt < 8; nt++) {
                v[nt * 2 + 0] = acc[mt][nt][rr * 2 + 0] + bias[cb + nt * 8 + qc + 0];
                v[nt * 2 + 1] = acc[mt][nt][rr * 2 + 1] + bias[cb + nt * 8 + qc + 1];
            }
            if (MODE == 0) {
                const int which = cb >> 10;
                const int h = (cb & 1023) >> 6;
                const int b = mrow >> 11, s = mrow & 2047;
                const int bhx = b * NH + h;
                if (which < 2) {
                    // RoPE: pair (d, d+32) = (nt, nt+4), same e
                    #pragma unroll
                    for (int nt = 0; nt < 4; nt++)
                        #pragma unroll
                        for (int e = 0; e < 2; e++) {
                            const int d = nt * 8 + qc + e;
                            const float cc = g_cos[(s << 5) + d];
                            const float sn = g_sin[(s << 5) + d];
                            const float x = v[nt * 2 + e], y = v[(nt + 4) * 2 + e];
                            v[nt * 2 + e]       = x * cc - y * sn;
                            v[(nt + 4) * 2 + e] = y * cc + x * sn;
                        }
                    if (which == 0) {
                        #pragma unroll
                        for (int i = 0; i < 16; i++) v[i] *= 0.125f;  // softmax scale (exact)
                    }
                    __nv_bfloat16* dh = ((which == 0) ? g_Qhi : g_Khi) + ((size_t)bhx * SEQ + s) * HD;
                    __nv_bfloat16* dl = ((which == 0) ? g_Qlo : g_Klo) + ((size_t)bhx * SEQ + s) * HD;
                    #pragma unroll
                    for (int nt = 0; nt < 8; nt++) {
                        const int d = nt * 8 + qc;
                        *(uint32_t*)&dh[d] = packbf(v[nt * 2], v[nt * 2 + 1]);
                        *(uint32_t*)&dl[d] = packbf(bf16lo(v[nt * 2]), bf16lo(v[nt * 2 + 1]));
                    }
                } else {
                    // V: transposed bf16 hi/lo scatter [bh][d][s]
                    #pragma unroll
                    for (int nt = 0; nt < 8; nt++)
                        #pragma unroll
                        for (int e = 0; e < 2; e++) {
                            const int d = nt * 8 + qc + e;
                            const float x = v[nt * 2 + e];
                            const __nv_bfloat16 hx = __float2bfloat16(x);
                            const size_t o = ((size_t)bhx * HD + d) * SEQ + s;
                            g_VThi[o] = hx;
                            g_VTlo[o] = __float2bfloat16(x - __bfloat162float(hx));
                        }
                }
            } else {
                float* o = out + (size_t)mrow * 1024 + cb;
                #pragma unroll
                for (int nt = 0; nt < 8; nt++)
                    *(float2*)&o[nt * 8 + qc] = make_float2(v[nt * 2], v[nt * 2 + 1]);
            }
        }
    }
}

// ---------------- Flash attention v3: HMMA bf16 split-3 ----------------
// grid (16 q-tiles of 128 rows, 64 bh), 256 threads (8 warps x 16 q-rows).
// KV tile = 64 keys; smem: double-buffered {Khi,Klo,VThi,VTlo}[64][72] bf16.
#define TILE_B 9216          // 64*144 bytes per array
#define BUF_B  36864         // 4 arrays
__global__ __launch_bounds__(256, 1)
void attn3_kernel()
{
    extern __shared__ __align__(16) char sm[];
    const uint32_t smb = smem_u32(sm);
    const int tid = threadIdx.x, wid = tid >> 5, lane = tid & 31;
    const int gr = lane >> 2, qc = (lane & 3) * 2;
    const int qt = blockIdx.x, bh = blockIdx.y;

    // ---- Q fragments (hi/lo) from gmem, once ----
    const int r_lo = qt * 128 + wid * 16 + gr;
    const size_t qrow_lo = ((size_t)bh * SEQ + r_lo) * HD;
    const size_t qrow_hi = qrow_lo + 8 * HD;
    uint32_t qhi[4][4], qlo[4][4];
    #pragma unroll
    for (int j = 0; j < 4; j++) {
        qhi[j][0] = *(const uint32_t*)&g_Qhi[qrow_lo + 16 * j + qc];
        qhi[j][1] = *(const uint32_t*)&g_Qhi[qrow_hi + 16 * j + qc];
        qhi[j][2] = *(const uint32_t*)&g_Qhi[qrow_lo + 16 * j + 8 + qc];
        qhi[j][3] = *(const uint32_t*)&g_Qhi[qrow_hi + 16 * j + 8 + qc];
        qlo[j][0] = *(const uint32_t*)&g_Qlo[qrow_lo + 16 * j + qc];
        qlo[j][1] = *(const uint32_t*)&g_Qlo[qrow_hi + 16 * j + qc];
        qlo[j][2] = *(const uint32_t*)&g_Qlo[qrow_lo + 16 * j + 8 + qc];
        qlo[j][3] = *(const uint32_t*)&g_Qlo[qrow_hi + 16 * j + 8 + qc];
    }

    float oacc[8][4];
    #pragma unroll
    for (int nt = 0; nt < 8; nt++)
        #pragma unroll
        for (int e = 0; e < 4; e++) oacc[nt][e] = 0.f;
    float m0 = -INFINITY, m1 = -INFINITY, l0 = 0.f, l1 = 0.f;

    // ---- tile loader (cp.async, 8 x 16B per thread) ----
    auto load_tile = [&](int tk, int buf) {
        const size_t koff = ((size_t)bh * SEQ + tk * 64) * HD;
        const size_t voff = (size_t)bh * HD * SEQ + tk * 64;
        #pragma unroll
        for (int it = 0; it < 8; it++) {
            const int lin = tid + it * 256;
            const int arr = lin >> 9;
            const int row = (lin >> 3) & 63;
            const int col = lin & 7;
            const __nv_bfloat16* g;
            if (arr == 0)      g = g_Khi  + koff + row * HD + col * 8;
            else if (arr == 1) g = g_Klo  + koff + row * HD + col * 8;
            else if (arr == 2) g = g_VThi + voff + (size_t)row * SEQ + col * 8;
            else               g = g_VTlo + voff + (size_t)row * SEQ + col * 8;
            const uint32_t dst = smb + buf * BUF_B + arr * TILE_B + row * 144 + col * 16;
            asm volatile("cp.async.cg.shared.global [%0], [%1], 16;" :: "r"(dst), "l"(g));
        }
        asm volatile("cp.async.commit_group;" ::: "memory");
    };

    load_tile(0, 0);

    for (int t = 0; t < 32; t++) {
        const int buf = t & 1;
        asm volatile("cp.async.wait_group 0;" ::: "memory");
        __syncthreads();
        if (t + 1 < 32) load_tile(t + 1, buf ^ 1);

        const char* kb_hi = sm + buf * BUF_B;
        const char* kb_lo = kb_hi + TILE_B;
        const char* vb_hi = kb_hi + 2 * TILE_B;
        const char* vb_lo = kb_hi + 3 * TILE_B;

        // ---- S = Q K^T (split-3) ----
        float c[8][4];
        #pragma unroll
        for (int nt = 0; nt < 8; nt++)
            #pragma unroll
            for (int e = 0; e < 4; e++) c[nt][e] = 0.f;

        #pragma unroll
        for (int j = 0; j < 4; j++) {
            #pragma unroll
            for (int nt = 0; nt < 8; nt++) {
                const int off = (nt * 8 + gr) * 144 + (16 * j + qc) * 2;
                const uint32_t bh0 = *(const uint32_t*)(kb_hi + off);
                const uint32_t bh1 = *(const uint32_t*)(kb_hi + off + 16);
                mma16816(c[nt], qhi[j], bh0, bh1);
                mma16816(c[nt], qlo[j], bh0, bh1);
                const uint32_t bl0 = *(const uint32_t*)(kb_lo + off);
                const uint32_t bl1 = *(const uint32_t*)(kb_lo + off + 16);
                mma16816(c[nt], qhi[j], bl0, bl1);
            }
        }

        // ---- online softmax (rows gr / gr+8; 4-lane groups) ----
        float mx0 = -INFINITY, mx1 = -INFINITY;
        #pragma unroll
        for (int nt = 0; nt < 8; nt++) {
            mx0 = fmaxf(mx0, fmaxf(c[nt][0], c[nt][1]));
            mx1 = fmaxf(mx1, fmaxf(c[nt][2], c[nt][3]));
        }
        mx0 = fmaxf(mx0, __shfl_xor_sync(0xffffffffu, mx0, 1));
        mx0 = fmaxf(mx0, __shfl_xor_sync(0xffffffffu, mx0, 2));
        mx1 = fmaxf(mx1, __shfl_xor_sync(0xffffffffu, mx1, 1));
        mx1 = fmaxf(mx1, __shfl_xor_sync(0xffffffffu, mx1, 2));
        const float nm0 = fmaxf(m0, mx0), nm1 = fmaxf(m1, mx1);
        const float cr0 = __expf(m0 - nm0), cr1 = __expf(m1 - nm1);
        float s0 = 0.f, s1 = 0.f;
        #pragma unroll
        for (int nt = 0; nt < 8; nt++) {
            c[nt][0] = __expf(c[nt][0] - nm0);
            c[nt][1] = __expf(c[nt][1] - nm0);
            c[nt][2] = __expf(c[nt][2] - nm1);
            c[nt][3] = __expf(c[nt][3] - nm1);
            s0 += c[nt][0] + c[nt][1];
            s1 += c[nt][2] + c[nt][3];
        }
        s0 += __shfl_xor_sync(0xffffffffu, s0, 1);
        s0 += __shfl_xor_sync(0xffffffffu, s0, 2);
        s1 += __shfl_xor_sync(0xffffffffu, s1, 1);
        s1 += __shfl_xor_sync(0xffffffffu, s1, 2);
        m0 = nm0; m1 = nm1;
        l0 = l0 * cr0 + s0;
        l1 = l1 * cr1 + s1;
        #pragma unroll
        for (int nt = 0; nt < 8; nt++) {
            oacc[nt][0] *= cr0; oacc[nt][1] *= cr0;
            oacc[nt][2] *= cr1; oacc[nt][3] *= cr1;
        }

        // ---- P fragments in registers (C-layout -> A-layout, hi/lo split) ----
        uint32_t ahi[4][4], alo[4][4];
        #pragma unroll
        for (int j = 0; j < 4; j++) {
            const float* t0 = c[2 * j];
            const float* t1 = c[2 * j + 1];
            ahi[j][0] = packbf(t0[0], t0[1]);
            ahi[j][1] = packbf(t0[2], t0[3]);
            ahi[j][2] = packbf(t1[0], t1[1]);
            ahi[j][3] = packbf(t1[2], t1[3]);
            alo[j][0] = packbf(bf16lo(t0[0]), bf16lo(t0[1]));
            alo[j][1] = packbf(bf16lo(t0[2]), bf16lo(t0[3]));
            alo[j][2] = packbf(bf16lo(t1[0]), bf16lo(t1[1]));
            alo[j][3] = packbf(bf16lo(t1[2]), bf16lo(t1[3]));
        }

        // ---- O += P V (split-3; B = V^T tiles) ----
        #pragma unroll
        for (int j = 0; j < 4; j++) {
            #pragma unroll
            for (int nt = 0; nt < 8; nt++) {
                const int off = (nt * 8 + gr) * 144 + (16 * j + qc) * 2;
                const uint32_t vh0 = *(const uint32_t*)(vb_hi + off);
                const uint32_t vh1 = *(const uint32_t*)(vb_hi + off + 16);
                mma16816(oacc[nt], ahi[j], vh0, vh1);
                mma16816(oacc[nt], alo[j], vh0, vh1);
                const uint32_t vl0 = *(const uint32_t*)(vb_lo + off);
                const uint32_t vl1 = *(const uint32_t*)(vb_lo + off + 16);
                mma16816(oacc[nt], ahi[j], vl0, vl1);
            }
        }
    }

    // ---- finalize -> AOhi/AOlo [b][s][h*64+d] ----
    const float inv0 = 1.0f / l0, inv1 = 1.0f / l1;
    const int b = bh >> 4, h = bh & 15;
    const size_t o0 = ((size_t)b * SEQ + r_lo) * EMB + h * 64;
    const size_t o1 = o0 + (size_t)8 * EMB;
    #pragma unroll
    for (int nt = 0; nt < 8; nt++) {
        const int d = nt * 8 + qc;
        float x = oacc[nt][0] * inv0, y = oacc[nt][1] * inv0;
        *(uint32_t*)&g_AOhi[o0 + d] = packbf(x, y);
        *(uint32_t*)&g_AOlo[o0 + d] = packbf(bf16lo(x), bf16lo(y));
        x = oacc[nt][2] * inv1; y = oacc[nt][3] * inv1;
        *(uint32_t*)&g_AOhi[o1 + d] = packbf(x, y);
        *(uint32_t*)&g_AOlo[o1 + d] = packbf(bf16lo(x), bf16lo(y));
    }
}

// ---------------- launch ----------------
extern "C" void kernel_launch(void* const* d_in, const int* in_sizes, int n_in,
                              void* d_out, int out_size)
{
    const float* hidden = (const float*)d_in[0];
    const float* qkv_w  = (const float*)d_in[1];
    const float* qkv_b  = (const float*)d_in[2];
    const float* proj_w = (const float*)d_in[3];
    const float* proj_b = (const float*)d_in[4];
    float* out = (float*)d_out;

    const int GEMM_SMEM = 4 * 128 * GP * 2;   // 73728
    const int ATTN_SMEM = 2 * BUF_B;          // 73728
    cudaFuncSetAttribute(hmma_gemm<0>, cudaFuncAttributeMaxDynamicSharedMemorySize, GEMM_SMEM);
    cudaFuncSetAttribute(hmma_gemm<1>, cudaFuncAttributeMaxDynamicSharedMemorySize, GEMM_SMEM);
    cudaFuncSetAttribute(attn3_kernel, cudaFuncAttributeMaxDynamicSharedMemorySize, ATTN_SMEM);

    rope_table_kernel<<<256, 256>>>();
    split_kernel<<<8192, 256>>>(hidden, 0);
    split_kernel<<<3072, 256>>>(qkv_w, 1);
    split_kernel<<<1024, 256>>>(proj_w, 2);

    // QKV projection + bias + RoPE + bf16-split scatter
    hmma_gemm<0><<<dim3(24, 64), 256, GEMM_SMEM>>>(qkv_b, nullptr);

    // attention (HMMA split-3) -> AOhi/AOlo
    attn3_kernel<<<dim3(16, 64), 256, ATTN_SMEM>>>();

    // output projection
    hmma_gemm<1><<<dim3(8, 64), 256, GEMM_SMEM>>>(proj_b, out);
}

// round 16
// speedup vs baseline: 9.0521x; 1.2131x over previous
#include <cuda_runtime.h>
#include <cuda_bf16.h>
#include <cuda_fp16.h>
#include <math.h>
#include <stdint.h>

#define BSZ 4
#define SEQ 2048
#define EMB 1024
#define NH  16
#define HD  64
#define MTOT (BSZ*SEQ)   // 8192

// ---------------- scratch (device globals; no allocation allowed) ----------------
__device__ __align__(16) float g_cos[SEQ*32];
__device__ __align__(16) float g_sin[SEQ*32];
// dense GEMM operands (fp32 -> bf16 hi/lo splits)
__device__ __align__(16) __nv_bfloat16 g_Ahi [MTOT*EMB];
__device__ __align__(16) __nv_bfloat16 g_Alo [MTOT*EMB];
__device__ __align__(16) __nv_bfloat16 g_Whi [3*EMB*EMB];
__device__ __align__(16) __nv_bfloat16 g_Wlo [3*EMB*EMB];
__device__ __align__(16) __nv_bfloat16 g_Phi [EMB*EMB];
__device__ __align__(16) __nv_bfloat16 g_Plo [EMB*EMB];
// attention operands (fp16), written by QKV GEMM epilogue
__device__ __align__(16) __half g_Qh [BSZ*NH*SEQ*HD];   // [bh][s][d], pre-scaled 0.125, hi
__device__ __align__(16) __half g_Ql [BSZ*NH*SEQ*HD];   // lo
__device__ __align__(16) __half g_Kh [BSZ*NH*SEQ*HD];   // [bh][s][d], single fp16
__device__ __align__(16) __half g_VTh[BSZ*NH*HD*SEQ];   // [bh][d][s], hi
__device__ __align__(16) __half g_VTl[BSZ*NH*HD*SEQ];   // lo
// attention output, bf16 hi/lo (input of proj GEMM)
__device__ __align__(16) __nv_bfloat16 g_AOhi[MTOT*EMB];
__device__ __align__(16) __nv_bfloat16 g_AOlo[MTOT*EMB];

// ---------------- helpers ----------------
__device__ __forceinline__ uint32_t smem_u32(const void* p) {
    uint32_t a;
    asm("{ .reg .u64 t; cvta.to.shared.u64 t, %1; cvt.u32.u64 %0, t; }" : "=r"(a) : "l"(p));
    return a;
}
__device__ __forceinline__ uint32_t packbf(float x, float y) {   // lo=x, hi=y
    uint32_t r;
    asm("cvt.rn.bf16x2.f32 %0, %1, %2;" : "=r"(r) : "f"(y), "f"(x));
    return r;
}
__device__ __forceinline__ float bf16lo(float x) {
    return x - __bfloat162float(__float2bfloat16(x));
}
__device__ __forceinline__ uint32_t packh(float x, float y) {    // lo=x, hi=y
    uint32_t r;
    asm("cvt.rn.f16x2.f32 %0, %1, %2;" : "=r"(r) : "f"(y), "f"(x));
    return r;
}
__device__ __forceinline__ float h16lo(float x) {
    return x - __half2float(__float2half_rn(x));
}
// HMMA m16n8k16 bf16 -> f32
__device__ __forceinline__ void mma16816(float* c, const uint32_t* a,
                                         uint32_t b0, uint32_t b1) {
    asm volatile(
        "mma.sync.aligned.m16n8k16.row.col.f32.bf16.bf16.f32 "
        "{%0,%1,%2,%3}, {%4,%5,%6,%7}, {%8,%9}, {%0,%1,%2,%3};"
        : "+f"(c[0]), "+f"(c[1]), "+f"(c[2]), "+f"(c[3])
        : "r"(a[0]), "r"(a[1]), "r"(a[2]), "r"(a[3]), "r"(b0), "r"(b1));
}
// HMMA m16n8k16 fp16 -> f32
__device__ __forceinline__ void mma16816h(float* c, const uint32_t* a,
                                          uint32_t b0, uint32_t b1) {
    asm volatile(
        "mma.sync.aligned.m16n8k16.row.col.f32.f16.f16.f32 "
        "{%0,%1,%2,%3}, {%4,%5,%6,%7}, {%8,%9}, {%0,%1,%2,%3};"
        : "+f"(c[0]), "+f"(c[1]), "+f"(c[2]), "+f"(c[3])
        : "r"(a[0]), "r"(a[1]), "r"(a[2]), "r"(a[3]), "r"(b0), "r"(b1));
}
#define CP_ASYNC16(dst, src) \
    asm volatile("cp.async.cg.shared.global [%0], [%1], 16;" :: "r"(dst), "l"(src))
#define CP_COMMIT() asm volatile("cp.async.commit_group;" ::: "memory")
#define CP_WAIT0()  asm volatile("cp.async.wait_group 0;" ::: "memory")

// ---------------- fp32 -> bf16 hi/lo split (GEMM inputs) ----------------
__global__ __launch_bounds__(256) void split_kernel(const float* __restrict__ src, int sel) {
    __nv_bfloat16 *hi, *lo;
    if      (sel == 0) { hi = g_Ahi; lo = g_Alo; }
    else if (sel == 1) { hi = g_Whi; lo = g_Wlo; }
    else               { hi = g_Phi; lo = g_Plo; }
    const int i = (blockIdx.x * 256 + threadIdx.x) * 4;
    float4 v = *(const float4*)&src[i];
    float f[4] = {v.x, v.y, v.z, v.w};
    #pragma unroll
    for (int j = 0; j < 4; j += 2) {
        *(uint32_t*)&hi[i + j] = packbf(f[j], f[j + 1]);
        *(uint32_t*)&lo[i + j] = packbf(bf16lo(f[j]), bf16lo(f[j + 1]));
    }
}

// ---------------- RoPE table (fp64-exact) ----------------
__global__ void rope_table_kernel() {
    const int idx = blockIdx.x * blockDim.x + threadIdx.x;
    const int d = idx & 31, s = idx >> 5;
    const double inv = exp(-((double)d / 32.0) * log(10000.0));
    const float ang = (float)s * (float)inv;
    g_cos[idx] = (float)cos((double)ang);
    g_sin[idx] = (float)sin((double)ang);
}

// ---------------- HMMA bf16 split-3 GEMM (cp.async double-buffered) ----------------
// MODE 0: QKV -> bias + RoPE + fp16 scatter (Q hi/lo scaled 0.125; K single; V^T hi/lo)
// MODE 1: proj -> bias -> out row-major fp32
#define GP 72
#define GBUF 73728   // bytes per k-chunk buffer (4 arrays x 128 x 144B)
template<int MODE>
__global__ __launch_bounds__(256, 1)
void hmma_gemm(const float* __restrict__ bias, float* __restrict__ out)
{
    extern __shared__ __align__(16) char dynsmem[];
    const uint32_t smb = smem_u32(dynsmem);

    const int tid = threadIdx.x;
    const int wid = tid >> 5, lane = tid & 31;
    const int n0 = blockIdx.x * 128;
    const int m0 = blockIdx.y * 128;

    const __nv_bfloat16* Ah = ((MODE == 0) ? g_Ahi : g_AOhi) + (size_t)m0 * 1024;
    const __nv_bfloat16* Al = ((MODE == 0) ? g_Alo : g_AOlo) + (size_t)m0 * 1024;
    const __nv_bfloat16* Bh = ((MODE == 0) ? g_Whi : g_Phi) + (size_t)n0 * 1024;
    const __nv_bfloat16* Bl = ((MODE == 0) ? g_Wlo : g_Plo) + (size_t)n0 * 1024;
    const __nv_bfloat16* gs[4] = {Ah, Al, Bh, Bl};

    const int wm = wid >> 1, wn = wid & 1;
    const int gr = lane >> 2, qc = (lane & 3) * 2;

    float acc[2][8][4];
    #pragma unroll
    for (int mt = 0; mt < 2; mt++)
        #pragma unroll
        for (int nt = 0; nt < 8; nt++)
            #pragma unroll
            for (int e = 0; e < 4; e++) acc[mt][nt][e] = 0.f;

    // cp.async tile loader: 4 arrays x 128 rows x 8 lines = 4096 lines / 256 thr
    auto load_chunk = [&](int c, int buf) {
        #pragma unroll
        for (int it = 0; it < 16; it++) {
            const int lin = tid + it * 256;
            const int arr = lin >> 10;
            const int row = (lin >> 3) & 127;
            const int col = lin & 7;
            const __nv_bfloat16* g = gs[arr] + (size_t)row * 1024 + c * 64 + col * 8;
            const uint32_t dst = smb + buf * GBUF + arr * 18432 + row * 144 + col * 16;
            CP_ASYNC16(dst, g);
        }
        CP_COMMIT();
    };

    load_chunk(0, 0);

    for (int c = 0; c < 16; c++) {
        const int buf = c & 1;
        CP_WAIT0();
        __syncthreads();
        if (c + 1 < 16) load_chunk(c + 1, buf ^ 1);

        const __nv_bfloat16* base = (const __nv_bfloat16*)(dynsmem + buf * GBUF);
        const __nv_bfloat16* pAh = base + (wm * 32) * GP;
        const __nv_bfloat16* pAl = base + 128 * GP + (wm * 32) * GP;
        const __nv_bfloat16* pBh = base + 2 * 128 * GP + (wn * 64) * GP;
        const __nv_bfloat16* pBl = base + 3 * 128 * GP + (wn * 64) * GP;

        #pragma unroll
        for (int kk = 0; kk < 64; kk += 16) {
            uint32_t ah[2][4], al[2][4];
            #pragma unroll
            for (int mt = 0; mt < 2; mt++) {
                const __nv_bfloat16* a0 = pAh + (mt * 16 + gr) * GP + kk + qc;
                ah[mt][0] = *(const uint32_t*)(a0);
                ah[mt][1] = *(const uint32_t*)(a0 + 8 * GP);
                ah[mt][2] = *(const uint32_t*)(a0 + 8);
                ah[mt][3] = *(const uint32_t*)(a0 + 8 * GP + 8);
                const __nv_bfloat16* a1 = pAl + (mt * 16 + gr) * GP + kk + qc;
                al[mt][0] = *(const uint32_t*)(a1);
                al[mt][1] = *(const uint32_t*)(a1 + 8 * GP);
                al[mt][2] = *(const uint32_t*)(a1 + 8);
                al[mt][3] = *(const uint32_t*)(a1 + 8 * GP + 8);
            }
            #pragma unroll
            for (int nt = 0; nt < 8; nt++) {
                const __nv_bfloat16* b0 = pBh + (nt * 8 + gr) * GP + kk + qc;
                const uint32_t bh0 = *(const uint32_t*)(b0);
                const uint32_t bh1 = *(const uint32_t*)(b0 + 8);
                const __nv_bfloat16* b1 = pBl + (nt * 8 + gr) * GP + kk + qc;
                const uint32_t bl0 = *(const uint32_t*)(b1);
                const uint32_t bl1 = *(const uint32_t*)(b1 + 8);
                #pragma unroll
                for (int mt = 0; mt < 2; mt++) {
                    mma16816(acc[mt][nt], ah[mt], bh0, bh1);
                    mma16816(acc[mt][nt], ah[mt], bl0, bl1);
                    mma16816(acc[mt][nt], al[mt], bh0, bh1);
                }
            }
        }
        __syncthreads();
    }

    const int cb = n0 + wn * 64;
    #pragma unroll
    for (int mt = 0; mt < 2; mt++) {
        #pragma unroll
        for (int rr = 0; rr < 2; rr++) {
            const int mrow = m0 + wm * 32 + mt * 16 + gr + rr * 8;
            float v[16];
            #pragma unroll
            for (int nt = 0; nt < 8; nt++) {
                v[nt * 2 + 0] = acc[mt][nt][rr * 2 + 0] + bias[cb + nt * 8 + qc + 0];
                v[nt * 2 + 1] = acc[mt][nt][rr * 2 + 1] + bias[cb + nt * 8 + qc + 1];
            }
            if (MODE == 0) {
                const int which = cb >> 10;
                const int h = (cb & 1023) >> 6;
                const int b = mrow >> 11, s = mrow & 2047;
                const int bhx = b * NH + h;
                if (which < 2) {
                    // RoPE: pair (d, d+32) = (nt, nt+4), same e
                    #pragma unroll
                    for (int nt = 0; nt < 4; nt++)
                        #pragma unroll
                        for (int e = 0; e < 2; e++) {
                            const int d = nt * 8 + qc + e;
                            const float cc = g_cos[(s << 5) + d];
                            const float sn = g_sin[(s << 5) + d];
                            const float x = v[nt * 2 + e], y = v[(nt + 4) * 2 + e];
                            v[nt * 2 + e]       = x * cc - y * sn;
                            v[(nt + 4) * 2 + e] = y * cc + x * sn;
                        }
                    const size_t rowo = ((size_t)bhx * SEQ + s) * HD;
                    if (which == 0) {
                        #pragma unroll
                        for (int i = 0; i < 16; i++) v[i] *= 0.125f;  // exact softmax scale
                        #pragma unroll
                        for (int nt = 0; nt < 8; nt++) {
                            const int d = nt * 8 + qc;
                            *(uint32_t*)&g_Qh[rowo + d] = packh(v[nt * 2], v[nt * 2 + 1]);
                            *(uint32_t*)&g_Ql[rowo + d] = packh(h16lo(v[nt * 2]), h16lo(v[nt * 2 + 1]));
                        }
                    } else {
                        #pragma unroll
                        for (int nt = 0; nt < 8; nt++) {
                            const int d = nt * 8 + qc;
                            *(uint32_t*)&g_Kh[rowo + d] = packh(v[nt * 2], v[nt * 2 + 1]);
                        }
                    }
                } else {
                    // V: transposed fp16 hi/lo scatter [bh][d][s]
                    #pragma unroll
                    for (int nt = 0; nt < 8; nt++)
                        #pragma unroll
                        for (int e = 0; e < 2; e++) {
                            const int d = nt * 8 + qc + e;
                            const float x = v[nt * 2 + e];
                            const __half hx = __float2half_rn(x);
                            const size_t o = ((size_t)bhx * HD + d) * SEQ + s;
                            g_VTh[o] = hx;
                            g_VTl[o] = __float2half_rn(x - __half2float(hx));
                        }
                }
            } else {
                float* o = out + (size_t)mrow * 1024 + cb;
                #pragma unroll
                for (int nt = 0; nt < 8; nt++)
                    *(float2*)&o[nt * 8 + qc] = make_float2(v[nt * 2], v[nt * 2 + 1]);
            }
        }
    }
}

// ---------------- Flash attention v4: fp16 HMMA, 5 MMAs/unit ----------------
// grid (16 q-tiles of 128 rows, 64 bh), 256 threads (8 warps x 16 q-rows).
// KV tile = 64 keys; double-buffered {Kh, VTh, VTl}[64][72] fp16.
#define TILE_B 9216          // 64*144 bytes per array
#define BUF_B  27648         // 3 arrays
__global__ __launch_bounds__(256, 1)
void attn4_kernel()
{
    extern __shared__ __align__(16) char sm[];
    const uint32_t smb = smem_u32(sm);
    const int tid = threadIdx.x, wid = tid >> 5, lane = tid & 31;
    const int gr = lane >> 2, qc = (lane & 3) * 2;
    const int qt = blockIdx.x, bh = blockIdx.y;

    // ---- Q fragments (fp16 hi/lo) from gmem, once ----
    const int r_lo = qt * 128 + wid * 16 + gr;
    const size_t qrow_lo = ((size_t)bh * SEQ + r_lo) * HD;
    const size_t qrow_hi = qrow_lo + 8 * HD;
    uint32_t qh[4][4], ql[4][4];
    #pragma unroll
    for (int j = 0; j < 4; j++) {
        qh[j][0] = *(const uint32_t*)&g_Qh[qrow_lo + 16 * j + qc];
        qh[j][1] = *(const uint32_t*)&g_Qh[qrow_hi + 16 * j + qc];
        qh[j][2] = *(const uint32_t*)&g_Qh[qrow_lo + 16 * j + 8 + qc];
        qh[j][3] = *(const uint32_t*)&g_Qh[qrow_hi + 16 * j + 8 + qc];
        ql[j][0] = *(const uint32_t*)&g_Ql[qrow_lo + 16 * j + qc];
        ql[j][1] = *(const uint32_t*)&g_Ql[qrow_hi + 16 * j + qc];
        ql[j][2] = *(const uint32_t*)&g_Ql[qrow_lo + 16 * j + 8 + qc];
        ql[j][3] = *(const uint32_t*)&g_Ql[qrow_hi + 16 * j + 8 + qc];
    }

    float oacc[8][4];
    #pragma unroll
    for (int nt = 0; nt < 8; nt++)
        #pragma unroll
        for (int e = 0; e < 4; e++) oacc[nt][e] = 0.f;
    float m0 = -INFINITY, m1 = -INFINITY, l0 = 0.f, l1 = 0.f;

    // ---- tile loader: 3 arrays x 512 lines = 1536 lines / 256 thr ----
    auto load_tile = [&](int tk, int buf) {
        const size_t koff = ((size_t)bh * SEQ + tk * 64) * HD;
        const size_t voff = (size_t)bh * HD * SEQ + tk * 64;
        #pragma unroll
        for (int it = 0; it < 6; it++) {
            const int lin = tid + it * 256;
            const int arr = lin >> 9;
            const int row = (lin >> 3) & 63;
            const int col = lin & 7;
            const __half* g;
            if (arr == 0)      g = g_Kh  + koff + row * HD + col * 8;
            else if (arr == 1) g = g_VTh + voff + (size_t)row * SEQ + col * 8;
            else               g = g_VTl + voff + (size_t)row * SEQ + col * 8;
            const uint32_t dst = smb + buf * BUF_B + arr * TILE_B + row * 144 + col * 16;
            CP_ASYNC16(dst, g);
        }
        CP_COMMIT();
    };

    load_tile(0, 0);

    for (int t = 0; t < 32; t++) {
        const int buf = t & 1;
        CP_WAIT0();
        __syncthreads();
        if (t + 1 < 32) load_tile(t + 1, buf ^ 1);

        const char* kb = sm + buf * BUF_B;
        const char* vbh = kb + TILE_B;
        const char* vbl = kb + 2 * TILE_B;

        // ---- S = Q K^T : 2 MMAs/unit (K single fp16) ----
        float c[8][4];
        #pragma unroll
        for (int nt = 0; nt < 8; nt++)
            #pragma unroll
            for (int e = 0; e < 4; e++) c[nt][e] = 0.f;

        #pragma unroll
        for (int j = 0; j < 4; j++) {
            #pragma unroll
            for (int nt = 0; nt < 8; nt++) {
                const int off = (nt * 8 + gr) * 144 + (16 * j + qc) * 2;
                const uint32_t b0 = *(const uint32_t*)(kb + off);
                const uint32_t b1 = *(const uint32_t*)(kb + off + 16);
                mma16816h(c[nt], qh[j], b0, b1);
                mma16816h(c[nt], ql[j], b0, b1);
            }
        }

        // ---- online softmax (rows gr / gr+8; 4-lane groups) ----
        float mx0 = -INFINITY, mx1 = -INFINITY;
        #pragma unroll
        for (int nt = 0; nt < 8; nt++) {
            mx0 = fmaxf(mx0, fmaxf(c[nt][0], c[nt][1]));
            mx1 = fmaxf(mx1, fmaxf(c[nt][2], c[nt][3]));
        }
        mx0 = fmaxf(mx0, __shfl_xor_sync(0xffffffffu, mx0, 1));
        mx0 = fmaxf(mx0, __shfl_xor_sync(0xffffffffu, mx0, 2));
        mx1 = fmaxf(mx1, __shfl_xor_sync(0xffffffffu, mx1, 1));
        mx1 = fmaxf(mx1, __shfl_xor_sync(0xffffffffu, mx1, 2));
        const float nm0 = fmaxf(m0, mx0), nm1 = fmaxf(m1, mx1);
        const float cr0 = __expf(m0 - nm0), cr1 = __expf(m1 - nm1);
        float s0 = 0.f, s1 = 0.f;
        #pragma unroll
        for (int nt = 0; nt < 8; nt++) {
            c[nt][0] = __expf(c[nt][0] - nm0);
            c[nt][1] = __expf(c[nt][1] - nm0);
            c[nt][2] = __expf(c[nt][2] - nm1);
            c[nt][3] = __expf(c[nt][3] - nm1);
            s0 += c[nt][0] + c[nt][1];
            s1 += c[nt][2] + c[nt][3];
        }
        s0 += __shfl_xor_sync(0xffffffffu, s0, 1);
        s0 += __shfl_xor_sync(0xffffffffu, s0, 2);
        s1 += __shfl_xor_sync(0xffffffffu, s1, 1);
        s1 += __shfl_xor_sync(0xffffffffu, s1, 2);
        m0 = nm0; m1 = nm1;
        l0 = l0 * cr0 + s0;
        l1 = l1 * cr1 + s1;
        #pragma unroll
        for (int nt = 0; nt < 8; nt++) {
            oacc[nt][0] *= cr0; oacc[nt][1] *= cr0;
            oacc[nt][2] *= cr1; oacc[nt][3] *= cr1;
        }

        // ---- P fragments in registers (fp16 hi/lo) ----
        uint32_t ahi[4][4], alo[4][4];
        #pragma unroll
        for (int j = 0; j < 4; j++) {
            const float* t0 = c[2 * j];
            const float* t1 = c[2 * j + 1];
            ahi[j][0] = packh(t0[0], t0[1]);
            ahi[j][1] = packh(t0[2], t0[3]);
            ahi[j][2] = packh(t1[0], t1[1]);
            ahi[j][3] = packh(t1[2], t1[3]);
            alo[j][0] = packh(h16lo(t0[0]), h16lo(t0[1]));
            alo[j][1] = packh(h16lo(t0[2]), h16lo(t0[3]));
            alo[j][2] = packh(h16lo(t1[0]), h16lo(t1[1]));
            alo[j][3] = packh(h16lo(t1[2]), h16lo(t1[3]));
        }

        // ---- O += P V : 3 MMAs/unit (split-3) ----
        #pragma unroll
        for (int j = 0; j < 4; j++) {
            #pragma unroll
            for (int nt = 0; nt < 8; nt++) {
                const int off = (nt * 8 + gr) * 144 + (16 * j + qc) * 2;
                const uint32_t vh0 = *(const uint32_t*)(vbh + off);
                const uint32_t vh1 = *(const uint32_t*)(vbh + off + 16);
                mma16816h(oacc[nt], ahi[j], vh0, vh1);
                mma16816h(oacc[nt], alo[j], vh0, vh1);
                const uint32_t vl0 = *(const uint32_t*)(vbl + off);
                const uint32_t vl1 = *(const uint32_t*)(vbl + off + 16);
                mma16816h(oacc[nt], ahi[j], vl0, vl1);
            }
        }
    }

    // ---- finalize -> AOhi/AOlo [b][s][h*64+d] ----
    const float inv0 = 1.0f / l0, inv1 = 1.0f / l1;
    const int b = bh >> 4, h = bh & 15;
    const size_t o0 = ((size_t)b * SEQ + r_lo) * EMB + h * 64;
    const size_t o1 = o0 + (size_t)8 * EMB;
    #pragma unroll
    for (int nt = 0; nt < 8; nt++) {
        const int d = nt * 8 + qc;
        float x = oacc[nt][0] * inv0, y = oacc[nt][1] * inv0;
        *(uint32_t*)&g_AOhi[o0 + d] = packbf(x, y);
        *(uint32_t*)&g_AOlo[o0 + d] = packbf(bf16lo(x), bf16lo(y));
        x = oacc[nt][2] * inv1; y = oacc[nt][3] * inv1;
        *(uint32_t*)&g_AOhi[o1 + d] = packbf(x, y);
        *(uint32_t*)&g_AOlo[o1 + d] = packbf(bf16lo(x), bf16lo(y));
    }
}

// ---------------- launch ----------------
extern "C" void kernel_launch(void* const* d_in, const int* in_sizes, int n_in,
                              void* d_out, int out_size)
{
    const float* hidden = (const float*)d_in[0];
    const float* qkv_w  = (const float*)d_in[1];
    const float* qkv_b  = (const float*)d_in[2];
    const float* proj_w = (const float*)d_in[3];
    const float* proj_b = (const float*)d_in[4];
    float* out = (float*)d_out;

    const int GEMM_SMEM = 2 * GBUF;   // 147456
    const int ATTN_SMEM = 2 * BUF_B;  // 55296
    cudaFuncSetAttribute(hmma_gemm<0>, cudaFuncAttributeMaxDynamicSharedMemorySize, GEMM_SMEM);
    cudaFuncSetAttribute(hmma_gemm<1>, cudaFuncAttributeMaxDynamicSharedMemorySize, GEMM_SMEM);
    cudaFuncSetAttribute(attn4_kernel, cudaFuncAttributeMaxDynamicSharedMemorySize, ATTN_SMEM);

    rope_table_kernel<<<256, 256>>>();
    split_kernel<<<8192, 256>>>(hidden, 0);
    split_kernel<<<3072, 256>>>(qkv_w, 1);
    split_kernel<<<1024, 256>>>(proj_w, 2);

    // QKV projection + bias + RoPE + fp16 scatter
    hmma_gemm<0><<<dim3(24, 64), 256, GEMM_SMEM>>>(qkv_b, nullptr);

    // attention (fp16 HMMA, 5 MMA/unit) -> AOhi/AOlo
    attn4_kernel<<<dim3(16, 64), 256, ATTN_SMEM>>>();

    // output projection
    hmma_gemm<1><<<dim3(8, 64), 256, GEMM_SMEM>>>(proj_b, out);
}

// round 17
// speedup vs baseline: 10.7824x; 1.1911x over previous
#include <cuda_runtime.h>
#include <cuda_bf16.h>
#include <cuda_fp16.h>
#include <math.h>
#include <stdint.h>

#define BSZ 4
#define SEQ 2048
#define EMB 1024
#define NH  16
#define HD  64
#define MTOT (BSZ*SEQ)   // 8192

// ---------------- scratch (device globals; no allocation allowed) ----------------
__device__ __align__(16) float g_cos[SEQ*32];
__device__ __align__(16) float g_sin[SEQ*32];
// dense GEMM operands (fp32 -> bf16 hi/lo splits)
__device__ __align__(16) __nv_bfloat16 g_Ahi [MTOT*EMB];
__device__ __align__(16) __nv_bfloat16 g_Alo [MTOT*EMB];
__device__ __align__(16) __nv_bfloat16 g_Whi [3*EMB*EMB];
__device__ __align__(16) __nv_bfloat16 g_Wlo [3*EMB*EMB];
__device__ __align__(16) __nv_bfloat16 g_Phi [EMB*EMB];
__device__ __align__(16) __nv_bfloat16 g_Plo [EMB*EMB];
// attention operands (fp16 single precision per operand), written by QKV GEMM epilogue
__device__ __align__(16) __half g_Qh [BSZ*NH*SEQ*HD];   // [bh][s][d], pre-scaled 0.125
__device__ __align__(16) __half g_Kh [BSZ*NH*SEQ*HD];   // [bh][s][d]
__device__ __align__(16) __half g_VTh[BSZ*NH*HD*SEQ];   // [bh][d][s]  (transposed)
// attention output, bf16 hi/lo (input of proj GEMM)
__device__ __align__(16) __nv_bfloat16 g_AOhi[MTOT*EMB];
__device__ __align__(16) __nv_bfloat16 g_AOlo[MTOT*EMB];

// ---------------- helpers ----------------
__device__ __forceinline__ uint32_t smem_u32(const void* p) {
    uint32_t a;
    asm("{ .reg .u64 t; cvta.to.shared.u64 t, %1; cvt.u32.u64 %0, t; }" : "=r"(a) : "l"(p));
    return a;
}
__device__ __forceinline__ uint32_t packbf(float x, float y) {   // lo=x, hi=y
    uint32_t r;
    asm("cvt.rn.bf16x2.f32 %0, %1, %2;" : "=r"(r) : "f"(y), "f"(x));
    return r;
}
__device__ __forceinline__ float bf16lo(float x) {
    return x - __bfloat162float(__float2bfloat16(x));
}
__device__ __forceinline__ uint32_t packh(float x, float y) {    // lo=x, hi=y
    uint32_t r;
    asm("cvt.rn.f16x2.f32 %0, %1, %2;" : "=r"(r) : "f"(y), "f"(x));
    return r;
}
__device__ __forceinline__ float h16lo(float x) {
    return x - __half2float(__float2half_rn(x));
}
// HMMA m16n8k16 bf16 -> f32
__device__ __forceinline__ void mma16816(float* c, const uint32_t* a,
                                         uint32_t b0, uint32_t b1) {
    asm volatile(
        "mma.sync.aligned.m16n8k16.row.col.f32.bf16.bf16.f32 "
        "{%0,%1,%2,%3}, {%4,%5,%6,%7}, {%8,%9}, {%0,%1,%2,%3};"
        : "+f"(c[0]), "+f"(c[1]), "+f"(c[2]), "+f"(c[3])
        : "r"(a[0]), "r"(a[1]), "r"(a[2]), "r"(a[3]), "r"(b0), "r"(b1));
}
// HMMA m16n8k16 fp16 -> f32
__device__ __forceinline__ void mma16816h(float* c, const uint32_t* a,
                                          uint32_t b0, uint32_t b1) {
    asm volatile(
        "mma.sync.aligned.m16n8k16.row.col.f32.f16.f16.f32 "
        "{%0,%1,%2,%3}, {%4,%5,%6,%7}, {%8,%9}, {%0,%1,%2,%3};"
        : "+f"(c[0]), "+f"(c[1]), "+f"(c[2]), "+f"(c[3])
        : "r"(a[0]), "r"(a[1]), "r"(a[2]), "r"(a[3]), "r"(b0), "r"(b1));
}
#define CP_ASYNC16(dst, src) \
    asm volatile("cp.async.cg.shared.global [%0], [%1], 16;" :: "r"(dst), "l"(src))
#define CP_COMMIT() asm volatile("cp.async.commit_group;" ::: "memory")
#define CP_WAIT0()  asm volatile("cp.async.wait_group 0;" ::: "memory")

// ---------------- fp32 -> bf16 hi/lo split (GEMM inputs) ----------------
__global__ __launch_bounds__(256) void split_kernel(const float* __restrict__ src, int sel) {
    __nv_bfloat16 *hi, *lo;
    if      (sel == 0) { hi = g_Ahi; lo = g_Alo; }
    else if (sel == 1) { hi = g_Whi; lo = g_Wlo; }
    else               { hi = g_Phi; lo = g_Plo; }
    const int i = (blockIdx.x * 256 + threadIdx.x) * 4;
    float4 v = *(const float4*)&src[i];
    float f[4] = {v.x, v.y, v.z, v.w};
    #pragma unroll
    for (int j = 0; j < 4; j += 2) {
        *(uint32_t*)&hi[i + j] = packbf(f[j], f[j + 1]);
        *(uint32_t*)&lo[i + j] = packbf(bf16lo(f[j]), bf16lo(f[j + 1]));
    }
}

// ---------------- RoPE table (fp64-exact) ----------------
__global__ void rope_table_kernel() {
    const int idx = blockIdx.x * blockDim.x + threadIdx.x;
    const int d = idx & 31, s = idx >> 5;
    const double inv = exp(-((double)d / 32.0) * log(10000.0));
    const float ang = (float)s * (float)inv;
    g_cos[idx] = (float)cos((double)ang);
    g_sin[idx] = (float)sin((double)ang);
}

// ---------------- HMMA bf16 split-3 GEMM (cp.async double-buffered) ----------------
// MODE 0: QKV -> bias + RoPE + fp16 scatter (Q scaled 0.125; K; V^T)
// MODE 1: proj -> bias -> out row-major fp32
#define GP 72
#define GBUF 73728   // bytes per k-chunk buffer (4 arrays x 128 x 144B)
template<int MODE>
__global__ __launch_bounds__(256, 1)
void hmma_gemm(const float* __restrict__ bias, float* __restrict__ out)
{
    extern __shared__ __align__(16) char dynsmem[];
    const uint32_t smb = smem_u32(dynsmem);

    const int tid = threadIdx.x;
    const int wid = tid >> 5, lane = tid & 31;
    const int n0 = blockIdx.x * 128;
    const int m0 = blockIdx.y * 128;

    const __nv_bfloat16* Ah = ((MODE == 0) ? g_Ahi : g_AOhi) + (size_t)m0 * 1024;
    const __nv_bfloat16* Al = ((MODE == 0) ? g_Alo : g_AOlo) + (size_t)m0 * 1024;
    const __nv_bfloat16* Bh = ((MODE == 0) ? g_Whi : g_Phi) + (size_t)n0 * 1024;
    const __nv_bfloat16* Bl = ((MODE == 0) ? g_Wlo : g_Plo) + (size_t)n0 * 1024;
    const __nv_bfloat16* gs[4] = {Ah, Al, Bh, Bl};

    const int wm = wid >> 1, wn = wid & 1;
    const int gr = lane >> 2, qc = (lane & 3) * 2;

    float acc[2][8][4];
    #pragma unroll
    for (int mt = 0; mt < 2; mt++)
        #pragma unroll
        for (int nt = 0; nt < 8; nt++)
            #pragma unroll
            for (int e = 0; e < 4; e++) acc[mt][nt][e] = 0.f;

    auto load_chunk = [&](int c, int buf) {
        #pragma unroll
        for (int it = 0; it < 16; it++) {
            const int lin = tid + it * 256;
            const int arr = lin >> 10;
            const int row = (lin >> 3) & 127;
            const int col = lin & 7;
            const __nv_bfloat16* g = gs[arr] + (size_t)row * 1024 + c * 64 + col * 8;
            const uint32_t dst = smb + buf * GBUF + arr * 18432 + row * 144 + col * 16;
            CP_ASYNC16(dst, g);
        }
        CP_COMMIT();
    };

    load_chunk(0, 0);

    for (int c = 0; c < 16; c++) {
        const int buf = c & 1;
        CP_WAIT0();
        __syncthreads();
        if (c + 1 < 16) load_chunk(c + 1, buf ^ 1);

        const __nv_bfloat16* base = (const __nv_bfloat16*)(dynsmem + buf * GBUF);
        const __nv_bfloat16* pAh = base + (wm * 32) * GP;
        const __nv_bfloat16* pAl = base + 128 * GP + (wm * 32) * GP;
        const __nv_bfloat16* pBh = base + 2 * 128 * GP + (wn * 64) * GP;
        const __nv_bfloat16* pBl = base + 3 * 128 * GP + (wn * 64) * GP;

        #pragma unroll
        for (int kk = 0; kk < 64; kk += 16) {
            uint32_t ah[2][4], al[2][4];
            #pragma unroll
            for (int mt = 0; mt < 2; mt++) {
                const __nv_bfloat16* a0 = pAh + (mt * 16 + gr) * GP + kk + qc;
                ah[mt][0] = *(const uint32_t*)(a0);
                ah[mt][1] = *(const uint32_t*)(a0 + 8 * GP);
                ah[mt][2] = *(const uint32_t*)(a0 + 8);
                ah[mt][3] = *(const uint32_t*)(a0 + 8 * GP + 8);
                const __nv_bfloat16* a1 = pAl + (mt * 16 + gr) * GP + kk + qc;
                al[mt][0] = *(const uint32_t*)(a1);
                al[mt][1] = *(const uint32_t*)(a1 + 8 * GP);
                al[mt][2] = *(const uint32_t*)(a1 + 8);
                al[mt][3] = *(const uint32_t*)(a1 + 8 * GP + 8);
            }
            #pragma unroll
            for (int nt = 0; nt < 8; nt++) {
                const __nv_bfloat16* b0 = pBh + (nt * 8 + gr) * GP + kk + qc;
                const uint32_t bh0 = *(const uint32_t*)(b0);
                const uint32_t bh1 = *(const uint32_t*)(b0 + 8);
                const __nv_bfloat16* b1 = pBl + (nt * 8 + gr) * GP + kk + qc;
                const uint32_t bl0 = *(const uint32_t*)(b1);
                const uint32_t bl1 = *(const uint32_t*)(b1 + 8);
                #pragma unroll
                for (int mt = 0; mt < 2; mt++) {
                    mma16816(acc[mt][nt], ah[mt], bh0, bh1);
                    mma16816(acc[mt][nt], ah[mt], bl0, bl1);
                    mma16816(acc[mt][nt], al[mt], bh0, bh1);
                }
            }
        }
        __syncthreads();
    }

    const int cb = n0 + wn * 64;
    #pragma unroll
    for (int mt = 0; mt < 2; mt++) {
        #pragma unroll
        for (int rr = 0; rr < 2; rr++) {
            const int mrow = m0 + wm * 32 + mt * 16 + gr + rr * 8;
            float v[16];
            #pragma unroll
            for (int nt = 0; nt < 8; nt++) {
                v[nt * 2 + 0] = acc[mt][nt][rr * 2 + 0] + bias[cb + nt * 8 + qc + 0];
                v[nt * 2 + 1] = acc[mt][nt][rr * 2 + 1] + bias[cb + nt * 8 + qc + 1];
            }
            if (MODE == 0) {
                const int which = cb >> 10;
                const int h = (cb & 1023) >> 6;
                const int b = mrow >> 11, s = mrow & 2047;
                const int bhx = b * NH + h;
                if (which < 2) {
                    // RoPE: pair (d, d+32) = (nt, nt+4), same e
                    #pragma unroll
                    for (int nt = 0; nt < 4; nt++)
                        #pragma unroll
                        for (int e = 0; e < 2; e++) {
                            const int d = nt * 8 + qc + e;
                            const float cc = g_cos[(s << 5) + d];
                            const float sn = g_sin[(s << 5) + d];
                            const float x = v[nt * 2 + e], y = v[(nt + 4) * 2 + e];
                            v[nt * 2 + e]       = x * cc - y * sn;
                            v[(nt + 4) * 2 + e] = y * cc + x * sn;
                        }
                    const size_t rowo = ((size_t)bhx * SEQ + s) * HD;
                    if (which == 0) {
                        #pragma unroll
                        for (int i = 0; i < 16; i++) v[i] *= 0.125f;  // exact softmax scale
                        #pragma unroll
                        for (int nt = 0; nt < 8; nt++) {
                            const int d = nt * 8 + qc;
                            *(uint32_t*)&g_Qh[rowo + d] = packh(v[nt * 2], v[nt * 2 + 1]);
                        }
                    } else {
                        #pragma unroll
                        for (int nt = 0; nt < 8; nt++) {
                            const int d = nt * 8 + qc;
                            *(uint32_t*)&g_Kh[rowo + d] = packh(v[nt * 2], v[nt * 2 + 1]);
                        }
                    }
                } else {
                    // V: transposed fp16 scatter [bh][d][s]
                    #pragma unroll
                    for (int nt = 0; nt < 8; nt++)
                        #pragma unroll
                        for (int e = 0; e < 2; e++) {
                            const int d = nt * 8 + qc + e;
                            g_VTh[((size_t)bhx * HD + d) * SEQ + mrow % SEQ + 0] =
                                __float2half_rn(v[nt * 2 + e]);
                        }
                }
            } else {
                float* o = out + (size_t)mrow * 1024 + cb;
                #pragma unroll
                for (int nt = 0; nt < 8; nt++)
                    *(float2*)&o[nt * 8 + qc] = make_float2(v[nt * 2], v[nt * 2 + 1]);
            }
        }
    }
}

// ---------------- Flash attention v5: fp16 HMMA, 3 MMAs/unit ----------------
// grid (16 q-tiles of 128 rows, 64 bh), 256 threads (8 warps x 16 q-rows).
// KV tile = 64 keys; double-buffered {Kh, VTh}[64][72] fp16.
#define TILE_B 9216          // 64*144 bytes per array
#define BUF_B  18432         // 2 arrays
__global__ __launch_bounds__(256, 2)
void attn5_kernel()
{
    extern __shared__ __align__(16) char sm[];
    const uint32_t smb = smem_u32(sm);
    const int tid = threadIdx.x, wid = tid >> 5, lane = tid & 31;
    const int gr = lane >> 2, qc = (lane & 3) * 2;
    const int qt = blockIdx.x, bh = blockIdx.y;

    // ---- Q fragments (fp16) from gmem, once ----
    const int r_lo = qt * 128 + wid * 16 + gr;
    const size_t qrow_lo = ((size_t)bh * SEQ + r_lo) * HD;
    const size_t qrow_hi = qrow_lo + 8 * HD;
    uint32_t qh[4][4];
    #pragma unroll
    for (int j = 0; j < 4; j++) {
        qh[j][0] = *(const uint32_t*)&g_Qh[qrow_lo + 16 * j + qc];
        qh[j][1] = *(const uint32_t*)&g_Qh[qrow_hi + 16 * j + qc];
        qh[j][2] = *(const uint32_t*)&g_Qh[qrow_lo + 16 * j + 8 + qc];
        qh[j][3] = *(const uint32_t*)&g_Qh[qrow_hi + 16 * j + 8 + qc];
    }

    float oacc[8][4];
    #pragma unroll
    for (int nt = 0; nt < 8; nt++)
        #pragma unroll
        for (int e = 0; e < 4; e++) oacc[nt][e] = 0.f;
    float m0 = -INFINITY, m1 = -INFINITY, l0 = 0.f, l1 = 0.f;

    // ---- tile loader: 2 arrays x 512 lines = 1024 lines / 256 thr ----
    auto load_tile = [&](int tk, int buf) {
        const size_t koff = ((size_t)bh * SEQ + tk * 64) * HD;
        const size_t voff = (size_t)bh * HD * SEQ + tk * 64;
        #pragma unroll
        for (int it = 0; it < 4; it++) {
            const int lin = tid + it * 256;
            const int arr = lin >> 9;
            const int row = (lin >> 3) & 63;
            const int col = lin & 7;
            const __half* g = (arr == 0) ? (g_Kh + koff + row * HD + col * 8)
                                         : (g_VTh + voff + (size_t)row * SEQ + col * 8);
            const uint32_t dst = smb + buf * BUF_B + arr * TILE_B + row * 144 + col * 16;
            CP_ASYNC16(dst, g);
        }
        CP_COMMIT();
    };

    load_tile(0, 0);

    for (int t = 0; t < 32; t++) {
        const int buf = t & 1;
        CP_WAIT0();
        __syncthreads();
        if (t + 1 < 32) load_tile(t + 1, buf ^ 1);

        const char* kb = sm + buf * BUF_B;
        const char* vb = kb + TILE_B;

        // ---- S = Q K^T : 1 MMA/unit ----
        float c[8][4];
        #pragma unroll
        for (int nt = 0; nt < 8; nt++)
            #pragma unroll
            for (int e = 0; e < 4; e++) c[nt][e] = 0.f;

        #pragma unroll
        for (int j = 0; j < 4; j++) {
            #pragma unroll
            for (int nt = 0; nt < 8; nt++) {
                const int off = (nt * 8 + gr) * 144 + (16 * j + qc) * 2;
                const uint32_t b0 = *(const uint32_t*)(kb + off);
                const uint32_t b1 = *(const uint32_t*)(kb + off + 16);
                mma16816h(c[nt], qh[j], b0, b1);
            }
        }

        // ---- online softmax (rows gr / gr+8; 4-lane groups) ----
        float mx0 = -INFINITY, mx1 = -INFINITY;
        #pragma unroll
        for (int nt = 0; nt < 8; nt++) {
            mx0 = fmaxf(mx0, fmaxf(c[nt][0], c[nt][1]));
            mx1 = fmaxf(mx1, fmaxf(c[nt][2], c[nt][3]));
        }
        mx0 = fmaxf(mx0, __shfl_xor_sync(0xffffffffu, mx0, 1));
        mx0 = fmaxf(mx0, __shfl_xor_sync(0xffffffffu, mx0, 2));
        mx1 = fmaxf(mx1, __shfl_xor_sync(0xffffffffu, mx1, 1));
        mx1 = fmaxf(mx1, __shfl_xor_sync(0xffffffffu, mx1, 2));
        const float nm0 = fmaxf(m0, mx0), nm1 = fmaxf(m1, mx1);
        const float cr0 = __expf(m0 - nm0), cr1 = __expf(m1 - nm1);
        float s0 = 0.f, s1 = 0.f;
        #pragma unroll
        for (int nt = 0; nt < 8; nt++) {
            c[nt][0] = __expf(c[nt][0] - nm0);
            c[nt][1] = __expf(c[nt][1] - nm0);
            c[nt][2] = __expf(c[nt][2] - nm1);
            c[nt][3] = __expf(c[nt][3] - nm1);
            s0 += c[nt][0] + c[nt][1];
            s1 += c[nt][2] + c[nt][3];
        }
        s0 += __shfl_xor_sync(0xffffffffu, s0, 1);
        s0 += __shfl_xor_sync(0xffffffffu, s0, 2);
        s1 += __shfl_xor_sync(0xffffffffu, s1, 1);
        s1 += __shfl_xor_sync(0xffffffffu, s1, 2);
        m0 = nm0; m1 = nm1;
        l0 = l0 * cr0 + s0;
        l1 = l1 * cr1 + s1;
        #pragma unroll
        for (int nt = 0; nt < 8; nt++) {
            oacc[nt][0] *= cr0; oacc[nt][1] *= cr0;
            oacc[nt][2] *= cr1; oacc[nt][3] *= cr1;
        }

        // ---- P fragments in registers (fp16 hi/lo) ----
        uint32_t ahi[4][4], alo[4][4];
        #pragma unroll
        for (int j = 0; j < 4; j++) {
            const float* t0 = c[2 * j];
            const float* t1 = c[2 * j + 1];
            ahi[j][0] = packh(t0[0], t0[1]);
            ahi[j][1] = packh(t0[2], t0[3]);
            ahi[j][2] = packh(t1[0], t1[1]);
            ahi[j][3] = packh(t1[2], t1[3]);
            alo[j][0] = packh(h16lo(t0[0]), h16lo(t0[1]));
            alo[j][1] = packh(h16lo(t0[2]), h16lo(t0[3]));
            alo[j][2] = packh(h16lo(t1[0]), h16lo(t1[1]));
            alo[j][3] = packh(h16lo(t1[2]), h16lo(t1[3]));
        }

        // ---- O += P V : 2 MMAs/unit (P split, V single) ----
        #pragma unroll
        for (int j = 0; j < 4; j++) {
            #pragma unroll
            for (int nt = 0; nt < 8; nt++) {
                const int off = (nt * 8 + gr) * 144 + (16 * j + qc) * 2;
                const uint32_t vh0 = *(const uint32_t*)(vb + off);
                const uint32_t vh1 = *(const uint32_t*)(vb + off + 16);
                mma16816h(oacc[nt], ahi[j], vh0, vh1);
                mma16816h(oacc[nt], alo[j], vh0, vh1);
            }
        }
    }

    // ---- finalize -> AOhi/AOlo [b][s][h*64+d] ----
    const float inv0 = 1.0f / l0, inv1 = 1.0f / l1;
    const int b = bh >> 4, h = bh & 15;
    const size_t o0 = ((size_t)b * SEQ + r_lo) * EMB + h * 64;
    const size_t o1 = o0 + (size_t)8 * EMB;
    #pragma unroll
    for (int nt = 0; nt < 8; nt++) {
        const int d = nt * 8 + qc;
        float x = oacc[nt][0] * inv0, y = oacc[nt][1] * inv0;
        *(uint32_t*)&g_AOhi[o0 + d] = packbf(x, y);
        *(uint32_t*)&g_AOlo[o0 + d] = packbf(bf16lo(x), bf16lo(y));
        x = oacc[nt][2] * inv1; y = oacc[nt][3] * inv1;
        *(uint32_t*)&g_AOhi[o1 + d] = packbf(x, y);
        *(uint32_t*)&g_AOlo[o1 + d] = packbf(bf16lo(x), bf16lo(y));
    }
}

// ---------------- launch ----------------
extern "C" void kernel_launch(void* const* d_in, const int* in_sizes, int n_in,
                              void* d_out, int out_size)
{
    const float* hidden = (const float*)d_in[0];
    const float* qkv_w  = (const float*)d_in[1];
    const float* qkv_b  = (const float*)d_in[2];
    const float* proj_w = (const float*)d_in[3];
    const float* proj_b = (const float*)d_in[4];
    float* out = (float*)d_out;

    const int GEMM_SMEM = 2 * GBUF;   // 147456
    const int ATTN_SMEM = 2 * BUF_B;  // 36864
    cudaFuncSetAttribute(hmma_gemm<0>, cudaFuncAttributeMaxDynamicSharedMemorySize, GEMM_SMEM);
    cudaFuncSetAttribute(hmma_gemm<1>, cudaFuncAttributeMaxDynamicSharedMemorySize, GEMM_SMEM);
    cudaFuncSetAttribute(attn5_kernel, cudaFuncAttributeMaxDynamicSharedMemorySize, ATTN_SMEM);

    rope_table_kernel<<<256, 256>>>();
    split_kernel<<<8192, 256>>>(hidden, 0);
    split_kernel<<<3072, 256>>>(qkv_w, 1);
    split_kernel<<<1024, 256>>>(proj_w, 2);

    // QKV projection + bias + RoPE + fp16 scatter
    hmma_gemm<0><<<dim3(24, 64), 256, GEMM_SMEM>>>(qkv_b, nullptr);

    // attention (fp16 HMMA, 3 MMA/unit) -> AOhi/AOlo
    attn5_kernel<<<dim3(16, 64), 256, ATTN_SMEM>>>();

    // output projection
    hmma_gemm<1><<<dim3(8, 64), 256, GEMM_SMEM>>>(proj_b, out);
}